// round 3
// baseline (speedup 1.0000x reference)
#include <cuda_runtime.h>
#include <cuda_bf16.h>
#include <cstdint>

#define NN 8192
#define IND 512
#define HID 256
#define OUTD 64
#define KSPL 1536   // 3*IND: [Xhi | Xhi | Xlo] vs [Whi ; Wlo ; Whi]

// ---------------- scratch (device globals; no allocation allowed) ----------------
__device__ __nv_bfloat16 g_Xs[NN * KSPL];        // 25.2 MB split X
__device__ __nv_bfloat16 g_Ws[KSPL * HID];       // split W
__device__ float         g_H1f[NN * HID];        // fp32 H1
__device__ __nv_bfloat16 g_H1b[NN * HID];        // bf16 H1 (V matrix)
__device__ float g_s1[NN], g_s2[NN];
__device__ float g_u[NN], g_u2[NN], g_v[NN], g_v2[NN];
__device__ float g_M[1];
__device__ float g_H2[NN * HID];

// ---------------- mma helpers ----------------
__device__ __forceinline__ void ldsm4(uint32_t& r0, uint32_t& r1, uint32_t& r2, uint32_t& r3,
                                      const void* p) {
    uint32_t ad = (uint32_t)__cvta_generic_to_shared(p);
    asm volatile("ldmatrix.sync.aligned.m8n8.x4.shared.b16 {%0,%1,%2,%3}, [%4];"
                 : "=r"(r0), "=r"(r1), "=r"(r2), "=r"(r3) : "r"(ad));
}
__device__ __forceinline__ void ldsm4t(uint32_t& r0, uint32_t& r1, uint32_t& r2, uint32_t& r3,
                                       const void* p) {
    uint32_t ad = (uint32_t)__cvta_generic_to_shared(p);
    asm volatile("ldmatrix.sync.aligned.m8n8.x4.trans.shared.b16 {%0,%1,%2,%3}, [%4];"
                 : "=r"(r0), "=r"(r1), "=r"(r2), "=r"(r3) : "r"(ad));
}
__device__ __forceinline__ void mma16816(float* c, uint32_t a0, uint32_t a1, uint32_t a2,
                                         uint32_t a3, uint32_t b0, uint32_t b1) {
    asm volatile(
        "mma.sync.aligned.m16n8k16.row.col.f32.bf16.bf16.f32 "
        "{%0,%1,%2,%3}, {%4,%5,%6,%7}, {%8,%9}, {%0,%1,%2,%3};"
        : "+f"(c[0]), "+f"(c[1]), "+f"(c[2]), "+f"(c[3])
        : "r"(a0), "r"(a1), "r"(a2), "r"(a3), "r"(b0), "r"(b1));
}

// ---------------- prep: bf16 2-term splits ----------------
__global__ void k_split_x(const float* __restrict__ X) {
    int idx = blockIdx.x * blockDim.x + threadIdx.x;
    if (idx >= NN * IND) return;
    int i = idx / IND, k = idx % IND;
    float x = X[idx];
    __nv_bfloat16 hi = __float2bfloat16(x);
    __nv_bfloat16 lo = __float2bfloat16(x - __bfloat162float(hi));
    g_Xs[i * KSPL + k] = hi;
    g_Xs[i * KSPL + IND + k] = hi;
    g_Xs[i * KSPL + 2 * IND + k] = lo;
}
__global__ void k_split_w(const float* __restrict__ W) {
    int idx = blockIdx.x * blockDim.x + threadIdx.x;
    if (idx >= IND * HID) return;
    int k = idx / HID, n = idx % HID;
    float x = W[idx];
    __nv_bfloat16 hi = __float2bfloat16(x);
    __nv_bfloat16 lo = __float2bfloat16(x - __bfloat162float(hi));
    g_Ws[k * HID + n] = hi;
    g_Ws[(IND + k) * HID + n] = lo;
    g_Ws[(2 * IND + k) * HID + n] = hi;
}

// ---------------- GEMM1: H1[8192,256] = Xs @ Ws + b1 (K=1536, bf16 mma, fp32 acc) ----------------
__global__ __launch_bounds__(256) void k_gemm1(const float* __restrict__ b1) {
    __shared__ __align__(16) __nv_bfloat16 aT[64][72];    // 64 x 64 (+pad)
    __shared__ __align__(16) __nv_bfloat16 bT[64][264];   // 64 x 256 (+pad)
    int tid = threadIdx.x, lane = tid & 31, w = tid >> 5;
    int m0 = blockIdx.x * 64;
    int mi = (w >> 1) * 16, nb = (w & 1) * 128;
    float acc[16][4];
#pragma unroll
    for (int i = 0; i < 16; i++)
#pragma unroll
        for (int j = 0; j < 4; j++) acc[i][j] = 0.f;

    for (int k0 = 0; k0 < KSPL; k0 += 64) {
#pragma unroll
        for (int q = 0; q < 2; q++) {
            int lin = q * 256 + tid;
            int r = lin >> 3, c4 = lin & 7;
            *(uint4*)&aT[r][c4 * 8] = *(const uint4*)&g_Xs[(m0 + r) * KSPL + k0 + c4 * 8];
        }
#pragma unroll
        for (int q = 0; q < 8; q++) {
            int lin = q * 256 + tid;
            int r = lin >> 5, c4 = lin & 31;
            *(uint4*)&bT[r][c4 * 8] = *(const uint4*)&g_Ws[(k0 + r) * HID + c4 * 8];
        }
        __syncthreads();
#pragma unroll
        for (int ks = 0; ks < 64; ks += 16) {
            uint32_t a0, a1, a2, a3;
            {
                int g = lane >> 3;
                int r = (lane & 7) + (g & 1) * 8;
                int c = (g >> 1) * 8;
                ldsm4(a0, a1, a2, a3, &aT[mi + r][ks + c]);
            }
#pragma unroll
            for (int nt = 0; nt < 8; nt++) {
                uint32_t b0, b1r, b2, b3;
                int g = lane >> 3;
                int r = (lane & 7) + (g & 1) * 8;
                int c = (g >> 1) * 8;
                ldsm4t(b0, b1r, b2, b3, &bT[ks + r][nb + nt * 16 + c]);
                mma16816(acc[nt * 2], a0, a1, a2, a3, b0, b1r);
                mma16816(acc[nt * 2 + 1], a0, a1, a2, a3, b2, b3);
            }
        }
        __syncthreads();
    }
    int r0 = m0 + mi + (lane >> 2);
#pragma unroll
    for (int nt = 0; nt < 8; nt++)
#pragma unroll
        for (int h = 0; h < 2; h++) {
            int j = nt * 2 + h;
            int cb = nb + nt * 16 + h * 8 + (lane & 3) * 2;
            float h00 = acc[j][0] + b1[cb];
            float h01 = acc[j][1] + b1[cb + 1];
            float h10 = acc[j][2] + b1[cb];
            float h11 = acc[j][3] + b1[cb + 1];
            g_H1f[r0 * HID + cb] = h00;
            g_H1f[r0 * HID + cb + 1] = h01;
            g_H1f[(r0 + 8) * HID + cb] = h10;
            g_H1f[(r0 + 8) * HID + cb + 1] = h11;
            g_H1b[r0 * HID + cb] = __float2bfloat16(h00);
            g_H1b[r0 * HID + cb + 1] = __float2bfloat16(h01);
            g_H1b[(r0 + 8) * HID + cb] = __float2bfloat16(h10);
            g_H1b[(r0 + 8) * HID + cb + 1] = __float2bfloat16(h11);
        }
}

// ---------------- s1 = H1@a1, s2 = H1@a2 (one warp per row) ----------------
__global__ void k_s(const float* __restrict__ a) {
    int gw = (blockIdx.x * blockDim.x + threadIdx.x) >> 5;
    int lane = threadIdx.x & 31;
    if (gw >= NN) return;
    const float4* hrow = (const float4*)&g_H1f[gw * HID];
    float d1 = 0.f, d2 = 0.f;
#pragma unroll
    for (int q = 0; q < 2; q++) {
        float4 hv = hrow[lane * 2 + q];
        int cb = lane * 8 + q * 4;
        d1 += hv.x * a[cb] + hv.y * a[cb + 1] + hv.z * a[cb + 2] + hv.w * a[cb + 3];
        d2 += hv.x * a[HID + cb] + hv.y * a[HID + cb + 1] + hv.z * a[HID + cb + 2] +
              hv.w * a[HID + cb + 3];
    }
#pragma unroll
    for (int o = 16; o; o >>= 1) {
        d1 += __shfl_xor_sync(0xffffffffu, d1, o);
        d2 += __shfl_xor_sync(0xffffffffu, d2, o);
    }
    if (lane == 0) { g_s1[gw] = d1; g_s2[gw] = d2; }
}

// ---------------- M = max(s2) (single block) ----------------
__global__ void k_max() {
    __shared__ float red[1024];
    float m = -1e30f;
    for (int i = threadIdx.x; i < NN; i += 1024) m = fmaxf(m, g_s2[i]);
    red[threadIdx.x] = m;
    __syncthreads();
    for (int s = 512; s; s >>= 1) {
        if (threadIdx.x < s) red[threadIdx.x] = fmaxf(red[threadIdx.x], red[threadIdx.x + s]);
        __syncthreads();
    }
    if (threadIdx.x == 0) g_M[0] = red[0];
}

// ---------------- u/v factor precompute ----------------
__global__ void k_uv() {
    int i = blockIdx.x * blockDim.x + threadIdx.x;
    if (i >= NN) return;
    float M = g_M[0];
    float s1 = g_s1[i], s2 = g_s2[i];
    float t = s1 + M;
    float c = t > 0.f ? t : 0.2f * t;  // c_i = leakyrelu(s1_i + max s2): valid softmax shift
    g_u[i] = expf(s1 - c);
    g_u2[i] = expf(0.2f * s1 - c);
    g_v[i] = expf(s2);
    g_v2[i] = expf(0.2f * s2);
}

// ---------------- fused mask -> p-tile -> PV mma -> H2 = (P@H1)/Z ----------------
// smem layout offsets
#define PV_PT 0                       // 64 x 136 bf16  = 17408 B
#define PV_HT 17408                   // 128 x 264 bf16 = 67584 B
#define PV_F  84992                   // float arrays
#define PV_SMEM (84992 + (128 * 3 + 64 * 4) * 4)

__global__ __launch_bounds__(256) void k_pv(const int* __restrict__ A) {
    extern __shared__ __align__(16) char smem[];
    __nv_bfloat16(*pT)[136] = (__nv_bfloat16(*)[136])(smem + PV_PT);
    __nv_bfloat16(*hT)[264] = (__nv_bfloat16(*)[264])(smem + PV_HT);
    float* tS2 = (float*)(smem + PV_F);
    float* tV = tS2 + 128;
    float* tV2 = tV + 128;
    float* sS1 = tV2 + 128;
    float* sU = sS1 + 64;
    float* sU2 = sU + 64;
    float* sZ = sU2 + 64;

    int tid = threadIdx.x, lane = tid & 31, w = tid >> 5;
    int i0 = blockIdx.x * 64;
    int mi = (w >> 1) * 16, nb = (w & 1) * 128;

    if (tid < 64) {
        sS1[tid] = g_s1[i0 + tid];
        sU[tid] = g_u[i0 + tid];
        sU2[tid] = g_u2[i0 + tid];
        sZ[tid] = 0.f;
    }
    float acc[16][4];
#pragma unroll
    for (int i = 0; i < 16; i++)
#pragma unroll
        for (int j = 0; j < 4; j++) acc[i][j] = 0.f;
    __syncthreads();

    for (int jt = 0; jt < 64; jt++) {
        int j0 = jt * 128;
        // per-tile column factors
        if (tid < 128) {
            tS2[tid] = g_s2[j0 + tid];
            tV[tid] = g_v[j0 + tid];
        } else {
            tV2[tid - 128] = g_v2[j0 + tid - 128];
        }
        __syncthreads();  // prev mma done (pT/hT free) + factors visible

        // build p tile (64 x 128) + Z partials; each warp: one row x 32 consecutive j
#pragma unroll 4
        for (int ps = 0; ps < 32; ps++) {
            int il = ps * 2 + (tid >> 7);
            int jl = tid & 127;
            int aval = A[(i0 + il) * NN + j0 + jl];
            float p = 0.f;
            if (aval > 0) {
                float t = sS1[il] + tS2[jl];
                p = t > 0.f ? sU[il] * tV[jl] : sU2[il] * tV2[jl];
            }
            pT[il][jl] = __float2bfloat16(p);
            float zs = p;
#pragma unroll
            for (int o = 16; o; o >>= 1) zs += __shfl_xor_sync(0xffffffffu, zs, o);
            if (lane == 0) atomicAdd(&sZ[il], zs);
        }
        // load H1 tile (128 x 256 bf16)
#pragma unroll
        for (int q = 0; q < 16; q++) {
            int lin = q * 256 + tid;
            int r = lin >> 5, c4 = lin & 31;
            *(uint4*)&hT[r][c4 * 8] = *(const uint4*)&g_H1b[(j0 + r) * HID + c4 * 8];
        }
        __syncthreads();

        // mma: C[64x256] += p[64x128] @ H1t[128x256]
#pragma unroll
        for (int ks = 0; ks < 128; ks += 16) {
            uint32_t a0, a1, a2, a3;
            {
                int g = lane >> 3;
                int r = (lane & 7) + (g & 1) * 8;
                int c = (g >> 1) * 8;
                ldsm4(a0, a1, a2, a3, &pT[mi + r][ks + c]);
            }
#pragma unroll
            for (int nt = 0; nt < 8; nt++) {
                uint32_t b0, b1r, b2, b3;
                int g = lane >> 3;
                int r = (lane & 7) + (g & 1) * 8;
                int c = (g >> 1) * 8;
                ldsm4t(b0, b1r, b2, b3, &hT[ks + r][nb + nt * 16 + c]);
                mma16816(acc[nt * 2], a0, a1, a2, a3, b0, b1r);
                mma16816(acc[nt * 2 + 1], a0, a1, a2, a3, b2, b3);
            }
        }
    }
    __syncthreads();
    int r0 = mi + (lane >> 2);
    float iz0 = 1.f / sZ[r0];
    float iz1 = 1.f / sZ[r0 + 8];
#pragma unroll
    for (int nt = 0; nt < 8; nt++)
#pragma unroll
        for (int h = 0; h < 2; h++) {
            int j = nt * 2 + h;
            int cb = nb + nt * 16 + h * 8 + (lane & 3) * 2;
            g_H2[(i0 + r0) * HID + cb] = acc[j][0] * iz0;
            g_H2[(i0 + r0) * HID + cb + 1] = acc[j][1] * iz0;
            g_H2[(i0 + r0 + 8) * HID + cb] = acc[j][2] * iz1;
            g_H2[(i0 + r0 + 8) * HID + cb + 1] = acc[j][3] * iz1;
        }
}

// ---------------- out = sigmoid(H2 @ Omega + beta) ----------------
__global__ void k_out(const float* __restrict__ Omega, const float* __restrict__ beta,
                      float* __restrict__ out) {
    __shared__ float hs[4][HID];
    int r0 = blockIdx.x * 4;
    int tid = threadIdx.x;
    for (int q = tid; q < 4 * HID; q += 256) hs[q / HID][q % HID] = g_H2[(r0 + q / HID) * HID + q % HID];
    __syncthreads();
    int rl = tid >> 6, col = tid & 63;
    float s = beta[col];
    const float* hr = hs[rl];
#pragma unroll 8
    for (int k = 0; k < HID; k++) s += hr[k] * __ldg(&Omega[k * OUTD + col]);
    out[(r0 + rl) * OUTD + col] = 1.f / (1.f + expf(-s));
}

// ---------------- launch ----------------
extern "C" void kernel_launch(void* const* d_in, const int* in_sizes, int n_in,
                              void* d_out, int out_size) {
    const float* X = (const float*)d_in[0];
    const int* A = (const int*)d_in[1];
    const float* W1 = (const float*)d_in[2];
    const float* b1 = (const float*)d_in[3];
    const float* a = (const float*)d_in[4];
    const float* Omega = (const float*)d_in[5];
    const float* beta = (const float*)d_in[6];
    float* out = (float*)d_out;

    cudaFuncSetAttribute(k_pv, cudaFuncAttributeMaxDynamicSharedMemorySize, PV_SMEM);

    k_split_x<<<(NN * IND + 255) / 256, 256>>>(X);
    k_split_w<<<(IND * HID + 255) / 256, 256>>>(W1);
    k_gemm1<<<NN / 64, 256>>>(b1);
    k_s<<<NN / 8, 256>>>(a);
    k_max<<<1, 1024>>>();
    k_uv<<<NN / 256, 256>>>();
    k_pv<<<NN / 64, 256, PV_SMEM>>>(A);
    k_out<<<NN / 4, 256>>>(Omega, beta, out);
}

// round 4
// speedup vs baseline: 3.8626x; 3.8626x over previous
#include <cuda_runtime.h>
#include <cuda_bf16.h>
#include <cstdint>

#define NN 8192
#define IND 512
#define HID 256
#define OUTD 64
#define KSPL 1536   // 3*IND: [Xhi | Xhi | Xlo] vs [Whi ; Wlo ; Whi]

// ---------------- scratch (device globals; no allocation allowed) ----------------
__device__ __nv_bfloat16 g_Xs[NN * KSPL];
__device__ __nv_bfloat16 g_Ws[KSPL * HID];
__device__ float         g_H1f[NN * HID];
__device__ __nv_bfloat16 g_H1b[NN * HID];
__device__ float g_s1[NN], g_s2[NN];
__device__ float g_v[NN], g_v2[NN];
__device__ uint32_t g_up[NN], g_up2[NN];       // u_i / u2_i duplicated bf16x2
__device__ uint32_t g_vp[NN / 2], g_vp2[NN / 2];  // (v_{2i}, v_{2i+1}) bf16x2 pairs
__device__ float g_M[1];
__device__ float g_H2[NN * HID];

// ---------------- mma helpers ----------------
__device__ __forceinline__ void ldsm4(uint32_t& r0, uint32_t& r1, uint32_t& r2, uint32_t& r3,
                                      const void* p) {
    uint32_t ad = (uint32_t)__cvta_generic_to_shared(p);
    asm volatile("ldmatrix.sync.aligned.m8n8.x4.shared.b16 {%0,%1,%2,%3}, [%4];"
                 : "=r"(r0), "=r"(r1), "=r"(r2), "=r"(r3) : "r"(ad));
}
__device__ __forceinline__ void ldsm4t(uint32_t& r0, uint32_t& r1, uint32_t& r2, uint32_t& r3,
                                       const void* p) {
    uint32_t ad = (uint32_t)__cvta_generic_to_shared(p);
    asm volatile("ldmatrix.sync.aligned.m8n8.x4.trans.shared.b16 {%0,%1,%2,%3}, [%4];"
                 : "=r"(r0), "=r"(r1), "=r"(r2), "=r"(r3) : "r"(ad));
}
__device__ __forceinline__ void mma16816(float* c, uint32_t a0, uint32_t a1, uint32_t a2,
                                         uint32_t a3, uint32_t b0, uint32_t b1) {
    asm volatile(
        "mma.sync.aligned.m16n8k16.row.col.f32.bf16.bf16.f32 "
        "{%0,%1,%2,%3}, {%4,%5,%6,%7}, {%8,%9}, {%0,%1,%2,%3};"
        : "+f"(c[0]), "+f"(c[1]), "+f"(c[2]), "+f"(c[3])
        : "r"(a0), "r"(a1), "r"(a2), "r"(a3), "r"(b0), "r"(b1));
}

__device__ __forceinline__ __nv_bfloat162 asb2(uint32_t x) {
    return *reinterpret_cast<__nv_bfloat162*>(&x);
}
__device__ __forceinline__ uint32_t asu32(__nv_bfloat162 x) {
    return *reinterpret_cast<uint32_t*>(&x);
}

// ---------------- prep: bf16 2-term splits ----------------
__global__ void k_split_x(const float* __restrict__ X) {
    int idx = blockIdx.x * blockDim.x + threadIdx.x;
    if (idx >= NN * IND) return;
    int i = idx / IND, k = idx % IND;
    float x = X[idx];
    __nv_bfloat16 hi = __float2bfloat16(x);
    __nv_bfloat16 lo = __float2bfloat16(x - __bfloat162float(hi));
    g_Xs[i * KSPL + k] = hi;
    g_Xs[i * KSPL + IND + k] = hi;
    g_Xs[i * KSPL + 2 * IND + k] = lo;
}
__global__ void k_split_w(const float* __restrict__ W) {
    int idx = blockIdx.x * blockDim.x + threadIdx.x;
    if (idx >= IND * HID) return;
    int k = idx / HID, n = idx % HID;
    float x = W[idx];
    __nv_bfloat16 hi = __float2bfloat16(x);
    __nv_bfloat16 lo = __float2bfloat16(x - __bfloat162float(hi));
    g_Ws[k * HID + n] = hi;
    g_Ws[(IND + k) * HID + n] = lo;
    g_Ws[(2 * IND + k) * HID + n] = hi;
}

// ---------------- GEMM1: H1[8192,256] = Xs @ Ws + b1 ----------------
__global__ __launch_bounds__(256) void k_gemm1(const float* __restrict__ b1) {
    __shared__ __align__(16) __nv_bfloat16 aT[64][72];
    __shared__ __align__(16) __nv_bfloat16 bT[64][264];
    int tid = threadIdx.x, lane = tid & 31, w = tid >> 5;
    int m0 = blockIdx.x * 64;
    int mi = (w >> 1) * 16, nb = (w & 1) * 128;
    float acc[16][4];
#pragma unroll
    for (int i = 0; i < 16; i++)
#pragma unroll
        for (int j = 0; j < 4; j++) acc[i][j] = 0.f;

    for (int k0 = 0; k0 < KSPL; k0 += 64) {
#pragma unroll
        for (int q = 0; q < 2; q++) {
            int lin = q * 256 + tid;
            int r = lin >> 3, c4 = lin & 7;
            *(uint4*)&aT[r][c4 * 8] = *(const uint4*)&g_Xs[(m0 + r) * KSPL + k0 + c4 * 8];
        }
#pragma unroll
        for (int q = 0; q < 8; q++) {
            int lin = q * 256 + tid;
            int r = lin >> 5, c4 = lin & 31;
            *(uint4*)&bT[r][c4 * 8] = *(const uint4*)&g_Ws[(k0 + r) * HID + c4 * 8];
        }
        __syncthreads();
#pragma unroll
        for (int ks = 0; ks < 64; ks += 16) {
            uint32_t a0, a1, a2, a3;
            {
                int g = lane >> 3;
                int r = (lane & 7) + (g & 1) * 8;
                int c = (g >> 1) * 8;
                ldsm4(a0, a1, a2, a3, &aT[mi + r][ks + c]);
            }
#pragma unroll
            for (int nt = 0; nt < 8; nt++) {
                uint32_t b0, b1r, b2, b3;
                int g = lane >> 3;
                int r = (lane & 7) + (g & 1) * 8;
                int c = (g >> 1) * 8;
                ldsm4t(b0, b1r, b2, b3, &bT[ks + r][nb + nt * 16 + c]);
                mma16816(acc[nt * 2], a0, a1, a2, a3, b0, b1r);
                mma16816(acc[nt * 2 + 1], a0, a1, a2, a3, b2, b3);
            }
        }
        __syncthreads();
    }
    int r0 = m0 + mi + (lane >> 2);
#pragma unroll
    for (int nt = 0; nt < 8; nt++)
#pragma unroll
        for (int h = 0; h < 2; h++) {
            int j = nt * 2 + h;
            int cb = nb + nt * 16 + h * 8 + (lane & 3) * 2;
            float h00 = acc[j][0] + b1[cb];
            float h01 = acc[j][1] + b1[cb + 1];
            float h10 = acc[j][2] + b1[cb];
            float h11 = acc[j][3] + b1[cb + 1];
            g_H1f[r0 * HID + cb] = h00;
            g_H1f[r0 * HID + cb + 1] = h01;
            g_H1f[(r0 + 8) * HID + cb] = h10;
            g_H1f[(r0 + 8) * HID + cb + 1] = h11;
            g_H1b[r0 * HID + cb] = __float2bfloat16(h00);
            g_H1b[r0 * HID + cb + 1] = __float2bfloat16(h01);
            g_H1b[(r0 + 8) * HID + cb] = __float2bfloat16(h10);
            g_H1b[(r0 + 8) * HID + cb + 1] = __float2bfloat16(h11);
        }
}

// ---------------- s1 = H1@a1, s2 = H1@a2 ----------------
__global__ void k_s(const float* __restrict__ a) {
    int gw = (blockIdx.x * blockDim.x + threadIdx.x) >> 5;
    int lane = threadIdx.x & 31;
    if (gw >= NN) return;
    const float4* hrow = (const float4*)&g_H1f[gw * HID];
    float d1 = 0.f, d2 = 0.f;
#pragma unroll
    for (int q = 0; q < 2; q++) {
        float4 hv = hrow[lane * 2 + q];
        int cb = lane * 8 + q * 4;
        d1 += hv.x * a[cb] + hv.y * a[cb + 1] + hv.z * a[cb + 2] + hv.w * a[cb + 3];
        d2 += hv.x * a[HID + cb] + hv.y * a[HID + cb + 1] + hv.z * a[HID + cb + 2] +
              hv.w * a[HID + cb + 3];
    }
#pragma unroll
    for (int o = 16; o; o >>= 1) {
        d1 += __shfl_xor_sync(0xffffffffu, d1, o);
        d2 += __shfl_xor_sync(0xffffffffu, d2, o);
    }
    if (lane == 0) { g_s1[gw] = d1; g_s2[gw] = d2; }
}

// ---------------- M = max(s2) ----------------
__global__ void k_max() {
    __shared__ float red[1024];
    float m = -1e30f;
    for (int i = threadIdx.x; i < NN; i += 1024) m = fmaxf(m, g_s2[i]);
    red[threadIdx.x] = m;
    __syncthreads();
    for (int s = 512; s; s >>= 1) {
        if (threadIdx.x < s) red[threadIdx.x] = fmaxf(red[threadIdx.x], red[threadIdx.x + s]);
        __syncthreads();
    }
    if (threadIdx.x == 0) g_M[0] = red[0];
}

// ---------------- u/v factor precompute (packed bf16x2 outputs) ----------------
__global__ void k_uv() {
    int i = blockIdx.x * blockDim.x + threadIdx.x;
    if (i >= NN) return;
    float M = g_M[0];
    float s1 = g_s1[i], s2 = g_s2[i];
    float t = s1 + M;
    float c = t > 0.f ? t : 0.2f * t;  // valid softmax shift (monotone leaky_relu)
    float u = expf(s1 - c);
    float u2 = expf(0.2f * s1 - c);
    g_v[i] = expf(s2);
    g_v2[i] = expf(0.2f * s2);
    uint32_t ub = (uint32_t)__bfloat16_as_ushort(__float2bfloat16(u));
    g_up[i] = ub | (ub << 16);
    uint32_t u2b = (uint32_t)__bfloat16_as_ushort(__float2bfloat16(u2));
    g_up2[i] = u2b | (u2b << 16);
}
__global__ void k_pack() {
    int i = blockIdx.x * blockDim.x + threadIdx.x;
    if (i >= NN / 2) return;
    uint32_t v0 = (uint32_t)__bfloat16_as_ushort(__float2bfloat16(g_v[2 * i]));
    uint32_t v1 = (uint32_t)__bfloat16_as_ushort(__float2bfloat16(g_v[2 * i + 1]));
    g_vp[i] = v0 | (v1 << 16);
    uint32_t w0 = (uint32_t)__bfloat16_as_ushort(__float2bfloat16(g_v2[2 * i]));
    uint32_t w1 = (uint32_t)__bfloat16_as_ushort(__float2bfloat16(g_v2[2 * i + 1]));
    g_vp2[i] = w0 | (w1 << 16);
}

// ---------------- fused mask -> p-tile -> PV mma (+Z via ones-mma) ----------------
// smem layout:
//   hT[2][128][264] bf16  (double-buffered V tiles, cp.async)
//   pT[64][136] bf16
//   sZ[64] float
#define PV_HT_STRIDE (128 * 264 * 2)              // 67584 per buffer
#define PV_PT_OFF (2 * PV_HT_STRIDE)              // 135168
#define PV_SZ_OFF (PV_PT_OFF + 64 * 136 * 2)      // 152576
#define PV_SMEM (PV_SZ_OFF + 64 * 4)              // 152832

__device__ __forceinline__ void pv_issue_ht(uint32_t sm32, int buf, int j0, int tid) {
    const char* src = (const char*)(g_H1b + (size_t)j0 * HID);
    uint32_t dbase = sm32 + buf * PV_HT_STRIDE;
#pragma unroll
    for (int q = 0; q < 8; q++) {
        int cidx = q * 512 + tid;
        int r = cidx >> 5, cc = cidx & 31;
        uint32_t dst = dbase + r * 528 + cc * 16;
        asm volatile("cp.async.cg.shared.global [%0], [%1], 16;" ::"r"(dst),
                     "l"(src + r * 512 + cc * 16));
    }
}

__global__ __launch_bounds__(512, 1) void k_pv(const int* __restrict__ A) {
    extern __shared__ __align__(16) char smem[];
    uint32_t sm32 = (uint32_t)__cvta_generic_to_shared(smem);
    int tid = threadIdx.x, lane = tid & 31, wid = tid >> 5;
    int i0 = blockIdx.x * 64;
    int mi = (wid >> 2) * 16, nb = (wid & 3) * 64;
    int il = tid >> 3, jc = tid & 7;
    int rowbase = (i0 + il) * NN;
    __nv_bfloat162 UX = asb2(g_up[i0 + il]);
    __nv_bfloat162 UX2 = asb2(g_up2[i0 + il]);

    float acc[8][4], accz[4];
#pragma unroll
    for (int i = 0; i < 8; i++)
#pragma unroll
        for (int j = 0; j < 4; j++) acc[i][j] = 0.f;
#pragma unroll
    for (int j = 0; j < 4; j++) accz[j] = 0.f;

    // prologue: hT(0) into buf0, A tile 0 into registers
    pv_issue_ht(sm32, 0, 0, tid);
    asm volatile("cp.async.commit_group;" ::: "memory");
    int4 Ac[4];
    {
        const int4* ap = (const int4*)(A + rowbase) + (jc << 2);
#pragma unroll
        for (int q = 0; q < 4; q++) Ac[q] = __ldcs(ap + q);
    }

    const uint32_t ONES = 0x3F803F80u;

    for (int jt = 0; jt < 64; jt++) {
        int buf = jt & 1;
        int j0 = jt << 7;

        // column factors (L2-resident, tiny)
        const uint4* vp = (const uint4*)(g_vp + (j0 >> 1) + (jc << 3));
        uint4 vA = __ldg(vp), vB = __ldg(vp + 1);
        const uint4* wp = (const uint4*)(g_vp2 + (j0 >> 1) + (jc << 3));
        uint4 wA = __ldg(wp), wB = __ldg(wp + 1);

        // build 16 p entries: p = mask * max(u*v, u2*v2)   (packed bf16x2)
        uint32_t po[8];
        {
            uint32_t m;
#define PV_PAIR(dst, a0v, a1v, vv, ww)                                                   \
    m = __byte_perm((uint32_t)(a0v), (uint32_t)(a1v), 0x5410) * 0x3F80u;                 \
    dst = asu32(__hmul2(__hmax2(__hmul2(UX, asb2(vv)), __hmul2(UX2, asb2(ww))), asb2(m)));
            PV_PAIR(po[0], Ac[0].x, Ac[0].y, vA.x, wA.x)
            PV_PAIR(po[1], Ac[0].z, Ac[0].w, vA.y, wA.y)
            PV_PAIR(po[2], Ac[1].x, Ac[1].y, vA.z, wA.z)
            PV_PAIR(po[3], Ac[1].z, Ac[1].w, vA.w, wA.w)
            PV_PAIR(po[4], Ac[2].x, Ac[2].y, vB.x, wB.x)
            PV_PAIR(po[5], Ac[2].z, Ac[2].w, vB.y, wB.y)
            PV_PAIR(po[6], Ac[3].x, Ac[3].y, vB.z, wB.z)
            PV_PAIR(po[7], Ac[3].z, Ac[3].w, vB.w, wB.w)
#undef PV_PAIR
        }
        {
            char* pdst = smem + PV_PT_OFF + il * 272 + (jc << 5);
            *(uint4*)pdst = make_uint4(po[0], po[1], po[2], po[3]);
            *(uint4*)(pdst + 16) = make_uint4(po[4], po[5], po[6], po[7]);
        }

        if (jt < 63) {
            // prefetch next A tile into the (now dead) Ac registers
            const int4* apn = (const int4*)(A + rowbase + ((jt + 1) << 7)) + (jc << 2);
#pragma unroll
            for (int q = 0; q < 4; q++) Ac[q] = __ldcs(apn + q);
            // start next hT copy into the other buffer
            pv_issue_ht(sm32, buf ^ 1, (jt + 1) << 7, tid);
            asm volatile("cp.async.commit_group;" ::: "memory");
            asm volatile("cp.async.wait_group 1;" ::: "memory");
        } else {
            asm volatile("cp.async.wait_group 0;" ::: "memory");
        }
        __syncthreads();

        // mma: acc[64x256] += p[64x128] @ H1t[128x256]; Z via ones-column mma
        const char* hbase = smem + buf * PV_HT_STRIDE;
        const char* pbase = smem + PV_PT_OFF;
        int g = lane >> 3;
        int r = (lane & 7) + (g & 1) * 8;
        int c = (g >> 1) * 8;
#pragma unroll
        for (int ks = 0; ks < 128; ks += 16) {
            uint32_t a0, a1, a2, a3;
            ldsm4(a0, a1, a2, a3, pbase + (mi + r) * 272 + (ks + c) * 2);
            if ((wid & 3) == 0) mma16816(accz, a0, a1, a2, a3, ONES, ONES);
#pragma unroll
            for (int nt = 0; nt < 4; nt++) {
                uint32_t b0, b1r, b2, b3;
                ldsm4t(b0, b1r, b2, b3, hbase + (ks + r) * 528 + (nb + nt * 16 + c) * 2);
                mma16816(acc[nt * 2], a0, a1, a2, a3, b0, b1r);
                mma16816(acc[nt * 2 + 1], a0, a1, a2, a3, b2, b3);
            }
        }
        __syncthreads();
    }

    // Z to smem, then scaled epilogue
    float* sZ = (float*)(smem + PV_SZ_OFF);
    if (((wid & 3) == 0) && ((lane & 3) == 0)) {
        sZ[mi + (lane >> 2)] = accz[0];
        sZ[mi + 8 + (lane >> 2)] = accz[2];
    }
    __syncthreads();
    int r0 = mi + (lane >> 2);
    float iz0 = 1.f / sZ[r0];
    float iz1 = 1.f / sZ[r0 + 8];
#pragma unroll
    for (int nt = 0; nt < 4; nt++)
#pragma unroll
        for (int h = 0; h < 2; h++) {
            int j = nt * 2 + h;
            int cb = nb + nt * 16 + h * 8 + (lane & 3) * 2;
            g_H2[(i0 + r0) * HID + cb] = acc[j][0] * iz0;
            g_H2[(i0 + r0) * HID + cb + 1] = acc[j][1] * iz0;
            g_H2[(i0 + r0 + 8) * HID + cb] = acc[j][2] * iz1;
            g_H2[(i0 + r0 + 8) * HID + cb + 1] = acc[j][3] * iz1;
        }
}

// ---------------- out = sigmoid(H2 @ Omega + beta) ----------------
__global__ void k_out(const float* __restrict__ Omega, const float* __restrict__ beta,
                      float* __restrict__ out) {
    __shared__ float hs[4][HID];
    int r0 = blockIdx.x * 4;
    int tid = threadIdx.x;
    for (int q = tid; q < 4 * HID; q += 256)
        hs[q / HID][q % HID] = g_H2[(r0 + q / HID) * HID + q % HID];
    __syncthreads();
    int rl = tid >> 6, col = tid & 63;
    float s = beta[col];
    const float* hr = hs[rl];
#pragma unroll 8
    for (int k = 0; k < HID; k++) s += hr[k] * __ldg(&Omega[k * OUTD + col]);
    out[(r0 + rl) * OUTD + col] = 1.f / (1.f + expf(-s));
}

// ---------------- launch ----------------
extern "C" void kernel_launch(void* const* d_in, const int* in_sizes, int n_in,
                              void* d_out, int out_size) {
    const float* X = (const float*)d_in[0];
    const int* A = (const int*)d_in[1];
    const float* W1 = (const float*)d_in[2];
    const float* b1 = (const float*)d_in[3];
    const float* a = (const float*)d_in[4];
    const float* Omega = (const float*)d_in[5];
    const float* beta = (const float*)d_in[6];
    float* out = (float*)d_out;

    cudaFuncSetAttribute(k_pv, cudaFuncAttributeMaxDynamicSharedMemorySize, PV_SMEM);

    k_split_x<<<(NN * IND + 255) / 256, 256>>>(X);
    k_split_w<<<(IND * HID + 255) / 256, 256>>>(W1);
    k_gemm1<<<NN / 64, 256>>>(b1);
    k_s<<<NN / 8, 256>>>(a);
    k_max<<<1, 1024>>>();
    k_uv<<<NN / 256, 256>>>();
    k_pack<<<NN / 512, 256>>>();
    k_pv<<<NN / 64, 512, PV_SMEM>>>(A);
    k_out<<<NN / 4, 256>>>(Omega, beta, out);
}

// round 5
// speedup vs baseline: 6.5756x; 1.7024x over previous
#include <cuda_runtime.h>
#include <cuda_bf16.h>
#include <cstdint>

#define NN 8192
#define IND 512
#define HID 256
#define OUTD 64
#define KS2 1024    // split-K: [Xhi | Xlo]
#define NC 80       // padded out cols: G[0:64], s1=64, s2=65, pad to 80

// ---------------- scratch ----------------
__device__ __nv_bfloat16 g_Xs2[NN * KS2];   // 16.8 MB split X
__device__ __nv_bfloat16 g_Wt[KS2 * NC];    // split W-tilde [1024][80]
__device__ float g_bc[66];                  // bcG[0:64], c1=64, c2=65
__device__ __nv_bfloat16 g_Gb[NN * OUTD];   // G = H1@Omega, bf16, 1 MB (L2-resident)
__device__ float g_s1[NN], g_s2[NN];
__device__ uint32_t g_up[NN], g_up2[NN];    // u_i / u2_i duplicated bf16x2
__device__ uint32_t g_vp[NN / 2], g_vp2[NN / 2];
__device__ float g_M[1];

// ---------------- mma helpers ----------------
__device__ __forceinline__ void ldsm4(uint32_t& r0, uint32_t& r1, uint32_t& r2, uint32_t& r3,
                                      const void* p) {
    uint32_t ad = (uint32_t)__cvta_generic_to_shared(p);
    asm volatile("ldmatrix.sync.aligned.m8n8.x4.shared.b16 {%0,%1,%2,%3}, [%4];"
                 : "=r"(r0), "=r"(r1), "=r"(r2), "=r"(r3) : "r"(ad));
}
__device__ __forceinline__ void ldsm4t(uint32_t& r0, uint32_t& r1, uint32_t& r2, uint32_t& r3,
                                       const void* p) {
    uint32_t ad = (uint32_t)__cvta_generic_to_shared(p);
    asm volatile("ldmatrix.sync.aligned.m8n8.x4.trans.shared.b16 {%0,%1,%2,%3}, [%4];"
                 : "=r"(r0), "=r"(r1), "=r"(r2), "=r"(r3) : "r"(ad));
}
__device__ __forceinline__ void mma16816(float* c, uint32_t a0, uint32_t a1, uint32_t a2,
                                         uint32_t a3, uint32_t b0, uint32_t b1) {
    asm volatile(
        "mma.sync.aligned.m16n8k16.row.col.f32.bf16.bf16.f32 "
        "{%0,%1,%2,%3}, {%4,%5,%6,%7}, {%8,%9}, {%0,%1,%2,%3};"
        : "+f"(c[0]), "+f"(c[1]), "+f"(c[2]), "+f"(c[3])
        : "r"(a0), "r"(a1), "r"(a2), "r"(a3), "r"(b0), "r"(b1));
}
__device__ __forceinline__ __nv_bfloat162 asb2(uint32_t x) {
    return *reinterpret_cast<__nv_bfloat162*>(&x);
}
__device__ __forceinline__ uint32_t asu32(__nv_bfloat162 x) {
    return *reinterpret_cast<uint32_t*>(&x);
}

// ---------------- k_prep: W~ = [W1@Omega | W1@a1 | W1@a2] (split bf16) + bias consts ----
__global__ void k_prep(const float* __restrict__ W1, const float* __restrict__ b1,
                       const float* __restrict__ a, const float* __restrict__ Omega) {
    __shared__ float wrow[HID];
    int blk = blockIdx.x;   // 0..511: W1 row; 512: b1
    int tid = threadIdx.x;
    const float* src = (blk < IND) ? (W1 + blk * HID) : b1;
    for (int k = tid; k < HID; k += 128) wrow[k] = src[k];
    __syncthreads();
    if (tid >= NC) return;
    float val = 0.f;
    if (tid < 64) {
        for (int k = 0; k < HID; k++) val += wrow[k] * Omega[k * OUTD + tid];
    } else if (tid == 64) {
        for (int k = 0; k < HID; k++) val += wrow[k] * a[k];
    } else if (tid == 65) {
        for (int k = 0; k < HID; k++) val += wrow[k] * a[HID + k];
    }
    if (blk < IND) {
        __nv_bfloat16 hi = __float2bfloat16(val);
        float lo = val - __bfloat162float(hi);
        g_Wt[blk * NC + tid] = hi;
        g_Wt[(IND + blk) * NC + tid] = __float2bfloat16(lo);
    } else if (tid < 66) {
        g_bc[tid] = val;
    }
}

// ---------------- k_splitX: X -> [hi | lo] bf16 ----------------
__global__ void k_splitX(const float* __restrict__ X) {
    int idx = blockIdx.x * 256 + threadIdx.x;
    if (idx >= NN * IND) return;
    int i = idx >> 9, k = idx & 511;
    float x = X[idx];
    __nv_bfloat16 hi = __float2bfloat16(x);
    g_Xs2[i * KS2 + k] = hi;
    g_Xs2[i * KS2 + IND + k] = __float2bfloat16(x - __bfloat162float(hi));
}

// ---------------- k_sg: [G | s1 | s2] = Xs2 @ Wt (+ consts) ----------------
__global__ __launch_bounds__(256) void k_sg() {
    __shared__ __align__(16) __nv_bfloat16 aT[128][72];
    __shared__ __align__(16) __nv_bfloat16 bT[64][88];
    int tid = threadIdx.x, lane = tid & 31, w = tid >> 5;
    int m0 = blockIdx.x * 128;
    int mi = w * 16;
    float acc[10][4];
#pragma unroll
    for (int i = 0; i < 10; i++)
#pragma unroll
        for (int j = 0; j < 4; j++) acc[i][j] = 0.f;

    for (int k0 = 0; k0 < KS2; k0 += 64) {
#pragma unroll
        for (int q = 0; q < 4; q++) {
            int idx = q * 256 + tid;
            int r = idx >> 3, cc = idx & 7;
            *(uint4*)&aT[r][cc * 8] = *(const uint4*)&g_Xs2[(m0 + r) * KS2 + k0 + cc * 8];
        }
#pragma unroll
        for (int q = 0; q < 3; q++) {
            int idx = q * 256 + tid;
            if (idx < 640) {
                int r = idx / 10, cc = idx % 10;
                *(uint4*)&bT[r][cc * 8] = *(const uint4*)&g_Wt[(k0 + r) * NC + cc * 8];
            }
        }
        __syncthreads();
        int g = lane >> 3;
        int r = (lane & 7) + (g & 1) * 8;
        int c = (g >> 1) * 8;
#pragma unroll
        for (int ks = 0; ks < 64; ks += 16) {
            uint32_t a0, a1, a2, a3;
            ldsm4(a0, a1, a2, a3, &aT[mi + r][ks + c]);
#pragma unroll
            for (int nt = 0; nt < 5; nt++) {
                uint32_t b0, b1r, b2, b3;
                ldsm4t(b0, b1r, b2, b3, &bT[ks + r][nt * 16 + c]);
                mma16816(acc[nt * 2], a0, a1, a2, a3, b0, b1r);
                mma16816(acc[nt * 2 + 1], a0, a1, a2, a3, b2, b3);
            }
        }
        __syncthreads();
    }
    int r0 = m0 + mi + (lane >> 2);
    // G (cols 0-63) with bias bcG, stored bf16
#pragma unroll
    for (int nt = 0; nt < 4; nt++)
#pragma unroll
        for (int h = 0; h < 2; h++) {
            int j = nt * 2 + h;
            int cb = nt * 16 + h * 8 + (lane & 3) * 2;
            float b0v = g_bc[cb], b1v = g_bc[cb + 1];
            __nv_bfloat162 p0 = __floats2bfloat162_rn(acc[j][0] + b0v, acc[j][1] + b1v);
            __nv_bfloat162 p1 = __floats2bfloat162_rn(acc[j][2] + b0v, acc[j][3] + b1v);
            *(uint32_t*)&g_Gb[r0 * OUTD + cb] = asu32(p0);
            *(uint32_t*)&g_Gb[(r0 + 8) * OUTD + cb] = asu32(p1);
        }
    // s1 (col 64), s2 (col 65)
    if ((lane & 3) == 0) {
        g_s1[r0] = acc[8][0] + g_bc[64];
        g_s2[r0] = acc[8][1] + g_bc[65];
        g_s1[r0 + 8] = acc[8][2] + g_bc[64];
        g_s2[r0 + 8] = acc[8][3] + g_bc[65];
    }
}

// ---------------- M = max(s2) ----------------
__global__ void k_max() {
    __shared__ float red[1024];
    float m = -1e30f;
    for (int i = threadIdx.x; i < NN; i += 1024) m = fmaxf(m, g_s2[i]);
    red[threadIdx.x] = m;
    __syncthreads();
    for (int s = 512; s; s >>= 1) {
        if (threadIdx.x < s) red[threadIdx.x] = fmaxf(red[threadIdx.x], red[threadIdx.x + s]);
        __syncthreads();
    }
    if (threadIdx.x == 0) g_M[0] = red[0];
}

// ---------------- u/v factors, packed ----------------
__global__ void k_uvp() {
    int i = blockIdx.x * blockDim.x + threadIdx.x;
    if (i >= NN) return;
    float M = g_M[0];
    float s1 = g_s1[i], s2 = g_s2[i];
    float t = s1 + M;
    float c = t > 0.f ? t : 0.2f * t;  // valid softmax shift (leaky_relu monotone)
    float u = expf(s1 - c);
    float u2 = expf(0.2f * s1 - c);
    uint32_t ub = (uint32_t)__bfloat16_as_ushort(__float2bfloat16(u));
    g_up[i] = ub | (ub << 16);
    uint32_t u2b = (uint32_t)__bfloat16_as_ushort(__float2bfloat16(u2));
    g_up2[i] = u2b | (u2b << 16);
    if (i < NN / 2) {
        float sa = g_s2[2 * i], sb = g_s2[2 * i + 1];
        uint32_t v0 = (uint32_t)__bfloat16_as_ushort(__float2bfloat16(expf(sa)));
        uint32_t v1 = (uint32_t)__bfloat16_as_ushort(__float2bfloat16(expf(sb)));
        g_vp[i] = v0 | (v1 << 16);
        uint32_t w0 = (uint32_t)__bfloat16_as_ushort(__float2bfloat16(expf(0.2f * sa)));
        uint32_t w1 = (uint32_t)__bfloat16_as_ushort(__float2bfloat16(expf(0.2f * sb)));
        g_vp2[i] = w0 | (w1 << 16);
    }
}

// ---------------- k_pv: out = sigmoid( (P @ G)/Z + beta ) ----------------
// 256 CTAs x 256 threads; i-tile = 32 rows; j-loop = 64 tiles of 128.
__global__ __launch_bounds__(256) void k_pv(const int* __restrict__ A,
                                            const float* __restrict__ beta,
                                            float* __restrict__ out) {
    __shared__ __align__(16) __nv_bfloat16 gT[2][128][72];
    __shared__ __align__(16) __nv_bfloat16 pT[32][136];
    __shared__ float sZ[32];
    int tid = threadIdx.x, lane = tid & 31, wid = tid >> 5;
    int i0 = blockIdx.x * 32;
    int mi = (wid >> 2) * 16, nb = (wid & 3) * 16;
    int il = tid >> 3, jc = tid & 7;
    long rowbase = (long)(i0 + il) * NN;
    __nv_bfloat162 UX = asb2(g_up[i0 + il]);
    __nv_bfloat162 UX2 = asb2(g_up2[i0 + il]);

    float acc[2][4], accz[4];
#pragma unroll
    for (int j = 0; j < 4; j++) { acc[0][j] = 0.f; acc[1][j] = 0.f; accz[j] = 0.f; }

    // prologue: gT(0) into buf0; A tile 0 into registers
    {
        uint32_t dbase = (uint32_t)__cvta_generic_to_shared(&gT[0][0][0]);
        const char* src = (const char*)g_Gb;
#pragma unroll
        for (int q = 0; q < 4; q++) {
            int idx = q * 256 + tid;
            int r = idx >> 3, cc = idx & 7;
            asm volatile("cp.async.cg.shared.global [%0], [%1], 16;" ::"r"(
                             dbase + r * 144 + cc * 16),
                         "l"(src + r * 128 + cc * 16));
        }
        asm volatile("cp.async.commit_group;" ::: "memory");
    }
    int4 Ac[4];
    {
        const int4* ap = (const int4*)(A + rowbase) + (jc << 2);
#pragma unroll
        for (int q = 0; q < 4; q++) Ac[q] = __ldcs(ap + q);
    }

    const uint32_t ONES = 0x3F803F80u;

    for (int jt = 0; jt < 64; jt++) {
        int buf = jt & 1;
        int j0 = jt << 7;

        const uint4* vp = (const uint4*)(g_vp + (j0 >> 1) + (jc << 3));
        uint4 vA = __ldg(vp), vB = __ldg(vp + 1);
        const uint4* wp = (const uint4*)(g_vp2 + (j0 >> 1) + (jc << 3));
        uint4 wA = __ldg(wp), wB = __ldg(wp + 1);

        uint32_t po[8];
        {
            uint32_t m;
#define PV_PAIR(dst, a0v, a1v, vv, ww)                                                   \
    m = __byte_perm((uint32_t)(a0v), (uint32_t)(a1v), 0x5410) * 0x3F80u;                 \
    dst = asu32(__hmul2(__hmax2(__hmul2(UX, asb2(vv)), __hmul2(UX2, asb2(ww))), asb2(m)));
            PV_PAIR(po[0], Ac[0].x, Ac[0].y, vA.x, wA.x)
            PV_PAIR(po[1], Ac[0].z, Ac[0].w, vA.y, wA.y)
            PV_PAIR(po[2], Ac[1].x, Ac[1].y, vA.z, wA.z)
            PV_PAIR(po[3], Ac[1].z, Ac[1].w, vA.w, wA.w)
            PV_PAIR(po[4], Ac[2].x, Ac[2].y, vB.x, wB.x)
            PV_PAIR(po[5], Ac[2].z, Ac[2].w, vB.y, wB.y)
            PV_PAIR(po[6], Ac[3].x, Ac[3].y, vB.z, wB.z)
            PV_PAIR(po[7], Ac[3].z, Ac[3].w, vB.w, wB.w)
#undef PV_PAIR
        }
        {
            __nv_bfloat16* pdst = &pT[il][jc * 16];
            *(uint4*)pdst = make_uint4(po[0], po[1], po[2], po[3]);
            *(uint4*)(pdst + 8) = make_uint4(po[4], po[5], po[6], po[7]);
        }

        if (jt < 63) {
            const int4* apn = (const int4*)(A + rowbase + ((long)(jt + 1) << 7)) + (jc << 2);
#pragma unroll
            for (int q = 0; q < 4; q++) Ac[q] = __ldcs(apn + q);
            uint32_t dbase = (uint32_t)__cvta_generic_to_shared(&gT[buf ^ 1][0][0]);
            const char* src = (const char*)(g_Gb + ((long)(jt + 1) << 7) * OUTD);
#pragma unroll
            for (int q = 0; q < 4; q++) {
                int idx = q * 256 + tid;
                int r = idx >> 3, cc = idx & 7;
                asm volatile("cp.async.cg.shared.global [%0], [%1], 16;" ::"r"(
                                 dbase + r * 144 + cc * 16),
                             "l"(src + r * 128 + cc * 16));
            }
            asm volatile("cp.async.commit_group;" ::: "memory");
            asm volatile("cp.async.wait_group 1;" ::: "memory");
        } else {
            asm volatile("cp.async.wait_group 0;" ::: "memory");
        }
        __syncthreads();

        int g = lane >> 3;
        int r = (lane & 7) + (g & 1) * 8;
        int c = (g >> 1) * 8;
#pragma unroll
        for (int ks = 0; ks < 128; ks += 16) {
            uint32_t a0, a1, a2, a3;
            ldsm4(a0, a1, a2, a3, &pT[mi + r][ks + c]);
            if ((wid & 3) == 0) mma16816(accz, a0, a1, a2, a3, ONES, ONES);
            uint32_t b0, b1r, b2, b3;
            ldsm4t(b0, b1r, b2, b3, &gT[buf][ks + r][nb + c]);
            mma16816(acc[0], a0, a1, a2, a3, b0, b1r);
            mma16816(acc[1], a0, a1, a2, a3, b2, b3);
        }
        __syncthreads();
    }

    if (((wid & 3) == 0) && ((lane & 3) == 0)) {
        sZ[mi + (lane >> 2)] = accz[0];
        sZ[mi + 8 + (lane >> 2)] = accz[2];
    }
    __syncthreads();
    int r0 = mi + (lane >> 2);
    float iz0 = 1.f / sZ[r0];
    float iz1 = 1.f / sZ[r0 + 8];
#pragma unroll
    for (int h = 0; h < 2; h++) {
        int cb = nb + h * 8 + (lane & 3) * 2;
        float be0 = beta[cb], be1 = beta[cb + 1];
        out[(i0 + r0) * OUTD + cb] = 1.f / (1.f + expf(-(acc[h][0] * iz0 + be0)));
        out[(i0 + r0) * OUTD + cb + 1] = 1.f / (1.f + expf(-(acc[h][1] * iz0 + be1)));
        out[(i0 + r0 + 8) * OUTD + cb] = 1.f / (1.f + expf(-(acc[h][2] * iz1 + be0)));
        out[(i0 + r0 + 8) * OUTD + cb + 1] = 1.f / (1.f + expf(-(acc[h][3] * iz1 + be1)));
    }
}

// ---------------- launch ----------------
extern "C" void kernel_launch(void* const* d_in, const int* in_sizes, int n_in,
                              void* d_out, int out_size) {
    const float* X = (const float*)d_in[0];
    const int* A = (const int*)d_in[1];
    const float* W1 = (const float*)d_in[2];
    const float* b1 = (const float*)d_in[3];
    const float* a = (const float*)d_in[4];
    const float* Omega = (const float*)d_in[5];
    const float* beta = (const float*)d_in[6];
    float* out = (float*)d_out;

    k_prep<<<IND + 1, 128>>>(W1, b1, a, Omega);
    k_splitX<<<(NN * IND + 255) / 256, 256>>>(X);
    k_sg<<<NN / 128, 256>>>();
    k_max<<<1, 1024>>>();
    k_uvp<<<NN / 256, 256>>>();
    k_pv<<<NN / 32, 256>>>(A, beta, out);
}

// round 10
// speedup vs baseline: 6.8223x; 1.0375x over previous
#include <cuda_runtime.h>
#include <cuda_bf16.h>
#include <cstdint>

#define NN 8192
#define IND 512
#define HID 256
#define OUTD 64
#define KS2 1024    // split-K: [Xhi | Xlo]
#define NC 80       // Wt cols: G[0:64], s1=64, s2=65, pad to 80
#define NJT 64      // j-tiles of 128 per CTA

// ---------------- scratch ----------------
__device__ __nv_bfloat16 g_Xs2[NN * KS2];   // 16.8 MB split X
__device__ __nv_bfloat16 g_Wt[KS2 * NC];    // split W-tilde
__device__ float g_bc[66];
__device__ __nv_bfloat16 g_Gb[NN * OUTD];   // G = H1@Omega + b, bf16 row-major (L2-resident)
__device__ float g_s1[NN], g_s2[NN];
__device__ uint32_t g_up[NN], g_up2[NN];    // u_i / u2_i duplicated bf16x2
__device__ uint32_t g_vp[NN / 2], g_vp2[NN / 2];
__device__ uint32_t g_Mu;

// ---------------- mma helpers ----------------
__device__ __forceinline__ void ldsm4(uint32_t& r0, uint32_t& r1, uint32_t& r2, uint32_t& r3,
                                      const void* p) {
    uint32_t ad = (uint32_t)__cvta_generic_to_shared(p);
    asm volatile("ldmatrix.sync.aligned.m8n8.x4.shared.b16 {%0,%1,%2,%3}, [%4];"
                 : "=r"(r0), "=r"(r1), "=r"(r2), "=r"(r3) : "r"(ad));
}
__device__ __forceinline__ void ldsm4t(uint32_t& r0, uint32_t& r1, uint32_t& r2, uint32_t& r3,
                                       const void* p) {
    uint32_t ad = (uint32_t)__cvta_generic_to_shared(p);
    asm volatile("ldmatrix.sync.aligned.m8n8.x4.trans.shared.b16 {%0,%1,%2,%3}, [%4];"
                 : "=r"(r0), "=r"(r1), "=r"(r2), "=r"(r3) : "r"(ad));
}
__device__ __forceinline__ void mma16816(float* c, uint32_t a0, uint32_t a1, uint32_t a2,
                                         uint32_t a3, uint32_t b0, uint32_t b1) {
    asm volatile(
        "mma.sync.aligned.m16n8k16.row.col.f32.bf16.bf16.f32 "
        "{%0,%1,%2,%3}, {%4,%5,%6,%7}, {%8,%9}, {%0,%1,%2,%3};"
        : "+f"(c[0]), "+f"(c[1]), "+f"(c[2]), "+f"(c[3])
        : "r"(a0), "r"(a1), "r"(a2), "r"(a3), "r"(b0), "r"(b1));
}
__device__ __forceinline__ __nv_bfloat162 asb2(uint32_t x) {
    return *reinterpret_cast<__nv_bfloat162*>(&x);
}
__device__ __forceinline__ uint32_t asu32(__nv_bfloat162 x) {
    return *reinterpret_cast<uint32_t*>(&x);
}

// ---------------- k_prep: W~ = [W1@Omega | W1@a1 | W1@a2] + bias consts ----------------
__global__ void k_prep(const float* __restrict__ W1, const float* __restrict__ b1,
                       const float* __restrict__ a, const float* __restrict__ Omega) {
    __shared__ float wrow[HID];
    int blk = blockIdx.x;   // 0..511: W1 row; 512: b1
    int tid = threadIdx.x;
    const float* src = (blk < IND) ? (W1 + blk * HID) : b1;
    for (int k = tid; k < HID; k += 128) wrow[k] = src[k];
    __syncthreads();
    if (blk == IND && tid == 80) g_Mu = 0u;   // reset ordered-max accumulator
    if (tid >= NC) return;
    float val = 0.f;
    if (tid < 64) {
        for (int k = 0; k < HID; k++) val += wrow[k] * Omega[k * OUTD + tid];
    } else if (tid == 64) {
        for (int k = 0; k < HID; k++) val += wrow[k] * a[k];
    } else if (tid == 65) {
        for (int k = 0; k < HID; k++) val += wrow[k] * a[HID + k];
    }
    if (blk < IND) {
        __nv_bfloat16 hi = __float2bfloat16(val);
        float lo = val - __bfloat162float(hi);
        g_Wt[blk * NC + tid] = hi;
        g_Wt[(IND + blk) * NC + tid] = __float2bfloat16(lo);
    } else if (tid < 66) {
        g_bc[tid] = val;
    }
}

// ---------------- k_splitX ----------------
__global__ void k_splitX(const float* __restrict__ X) {
    int idx = blockIdx.x * 256 + threadIdx.x;
    if (idx >= NN * IND) return;
    int i = idx >> 9, k = idx & 511;
    float x = X[idx];
    __nv_bfloat16 hi = __float2bfloat16(x);
    g_Xs2[i * KS2 + k] = hi;
    g_Xs2[i * KS2 + IND + k] = __float2bfloat16(x - __bfloat162float(hi));
}

// ---------------- k_sg: [G | s1 | s2] = Xs2 @ Wt (128 CTAs, 64-row tiles) ----------------
__global__ __launch_bounds__(256) void k_sg() {
    __shared__ __align__(16) __nv_bfloat16 aT[64][72];
    __shared__ __align__(16) __nv_bfloat16 bT[64][88];
    int tid = threadIdx.x, lane = tid & 31, w = tid >> 5;
    int m0 = blockIdx.x * 64;
    int mi = (w >> 1) * 16;
    int cw = w & 1;   // 0: nt 0..2 (cols 0-47), 1: nt 3..4 (cols 48-79)
    float acc[6][4];
#pragma unroll
    for (int i = 0; i < 6; i++)
#pragma unroll
        for (int j = 0; j < 4; j++) acc[i][j] = 0.f;

    for (int k0 = 0; k0 < KS2; k0 += 64) {
#pragma unroll
        for (int q = 0; q < 2; q++) {
            int idx = q * 256 + tid;
            int rr = idx >> 3, cc = idx & 7;
            *(uint4*)&aT[rr][cc * 8] = *(const uint4*)&g_Xs2[(m0 + rr) * KS2 + k0 + cc * 8];
        }
#pragma unroll
        for (int q = 0; q < 3; q++) {
            int idx = q * 256 + tid;
            if (idx < 640) {
                int rr = idx / 10, cc = idx % 10;
                *(uint4*)&bT[rr][cc * 8] = *(const uint4*)&g_Wt[(k0 + rr) * NC + cc * 8];
            }
        }
        __syncthreads();
        int g = lane >> 3;
        int r = (lane & 7) + (g & 1) * 8;
        int c = (g >> 1) * 8;
#pragma unroll
        for (int ks = 0; ks < 64; ks += 16) {
            uint32_t a0, a1, a2, a3;
            ldsm4(a0, a1, a2, a3, &aT[mi + r][ks + c]);
            if (cw == 0) {
#pragma unroll
                for (int nt = 0; nt < 3; nt++) {
                    uint32_t b0, b1r, b2, b3;
                    ldsm4t(b0, b1r, b2, b3, &bT[ks + r][nt * 16 + c]);
                    mma16816(acc[nt * 2], a0, a1, a2, a3, b0, b1r);
                    mma16816(acc[nt * 2 + 1], a0, a1, a2, a3, b2, b3);
                }
            } else {
#pragma unroll
                for (int nt2 = 0; nt2 < 2; nt2++) {
                    uint32_t b0, b1r, b2, b3;
                    ldsm4t(b0, b1r, b2, b3, &bT[ks + r][(nt2 + 3) * 16 + c]);
                    mma16816(acc[nt2 * 2], a0, a1, a2, a3, b0, b1r);
                    mma16816(acc[nt2 * 2 + 1], a0, a1, a2, a3, b2, b3);
                }
            }
        }
        __syncthreads();
    }
    int r0 = m0 + mi + (lane >> 2);
    if (cw == 0) {
#pragma unroll
        for (int nt = 0; nt < 3; nt++)
#pragma unroll
            for (int h = 0; h < 2; h++) {
                int j = nt * 2 + h;
                int cb = nt * 16 + h * 8 + (lane & 3) * 2;
                float b0v = g_bc[cb], b1v = g_bc[cb + 1];
                __nv_bfloat162 p0 = __floats2bfloat162_rn(acc[j][0] + b0v, acc[j][1] + b1v);
                __nv_bfloat162 p1 = __floats2bfloat162_rn(acc[j][2] + b0v, acc[j][3] + b1v);
                *(uint32_t*)&g_Gb[r0 * OUTD + cb] = asu32(p0);
                *(uint32_t*)&g_Gb[(r0 + 8) * OUTD + cb] = asu32(p1);
            }
    } else {
        // nt=3 -> G cols 48-63 (local acc[0],acc[1])
#pragma unroll
        for (int h = 0; h < 2; h++) {
            int cb = 48 + h * 8 + (lane & 3) * 2;
            float b0v = g_bc[cb], b1v = g_bc[cb + 1];
            __nv_bfloat162 p0 = __floats2bfloat162_rn(acc[h][0] + b0v, acc[h][1] + b1v);
            __nv_bfloat162 p1 = __floats2bfloat162_rn(acc[h][2] + b0v, acc[h][3] + b1v);
            *(uint32_t*)&g_Gb[r0 * OUTD + cb] = asu32(p0);
            *(uint32_t*)&g_Gb[(r0 + 8) * OUTD + cb] = asu32(p1);
        }
        // nt=4 h=0 -> cols 64 (s1), 65 (s2) in local acc[2]
        if ((lane & 3) == 0) {
            g_s1[r0] = acc[2][0] + g_bc[64];
            g_s2[r0] = acc[2][1] + g_bc[65];
            g_s1[r0 + 8] = acc[2][2] + g_bc[64];
            g_s2[r0 + 8] = acc[2][3] + g_bc[65];
        }
    }
}

// ---------------- k_max: parallel ordered-uint atomicMax ----------------
__global__ void k_max() {
    __shared__ uint32_t red[32];
    int i = blockIdx.x * 1024 + threadIdx.x;
    uint32_t u = __float_as_uint(g_s2[i]);
    u = (u & 0x80000000u) ? ~u : (u | 0x80000000u);
#pragma unroll
    for (int o = 16; o; o >>= 1) u = max(u, __shfl_xor_sync(0xffffffffu, u, o));
    if ((threadIdx.x & 31) == 0) red[threadIdx.x >> 5] = u;
    __syncthreads();
    if (threadIdx.x < 32) {
        u = red[threadIdx.x];
#pragma unroll
        for (int o = 16; o; o >>= 1) u = max(u, __shfl_xor_sync(0xffffffffu, u, o));
        if (threadIdx.x == 0) atomicMax(&g_Mu, u);
    }
}

// ---------------- k_uvp ----------------
__global__ void k_uvp() {
    int i = blockIdx.x * blockDim.x + threadIdx.x;
    if (i >= NN) return;
    uint32_t e = g_Mu;
    float M = (e & 0x80000000u) ? __uint_as_float(e & 0x7FFFFFFFu) : __uint_as_float(~e);
    float s1 = g_s1[i], s2 = g_s2[i];
    float t = s1 + M;
    float c = t > 0.f ? t : 0.2f * t;   // valid softmax shift (leaky_relu monotone)
    float u = expf(s1 - c);
    float u2 = expf(0.2f * s1 - c);
    uint32_t ub = (uint32_t)__bfloat16_as_ushort(__float2bfloat16(u));
    g_up[i] = ub | (ub << 16);
    uint32_t u2b = (uint32_t)__bfloat16_as_ushort(__float2bfloat16(u2));
    g_up2[i] = u2b | (u2b << 16);
    if (i < NN / 2) {
        float sa = g_s2[2 * i], sb = g_s2[2 * i + 1];
        uint32_t v0 = (uint32_t)__bfloat16_as_ushort(__float2bfloat16(expf(sa)));
        uint32_t v1 = (uint32_t)__bfloat16_as_ushort(__float2bfloat16(expf(sb)));
        g_vp[i] = v0 | (v1 << 16);
        uint32_t w0 = (uint32_t)__bfloat16_as_ushort(__float2bfloat16(expf(0.2f * sa)));
        uint32_t w1 = (uint32_t)__bfloat16_as_ushort(__float2bfloat16(expf(0.2f * sb)));
        g_vp2[i] = w0 | (w1 << 16);
    }
}

// ---------------- k_pv: out = sigmoid((P@G)/Z + beta), pipelined mma.sync ----------------
// smem: gT[3][128][72] bf16 (cp.async triple buffer), pT[2][32][136] bf16, sZ[32]
#define GT_STRIDE 18432                     // 128*144 B
#define OFF_GT 0                            // 3 * 18432 = 55296
#define OFF_PT 55296                        // 2 * 8704 = 17408
#define PT_STRIDE 8704                      // 32*272 B
#define OFF_SZ 72704
#define SMEM_PV 72832

__device__ __forceinline__ void pv_load_gt(uint32_t sm, int buf, int j0, int tid) {
    uint32_t dbase = sm + OFF_GT + buf * GT_STRIDE;
    const char* src = (const char*)(g_Gb + (size_t)j0 * OUTD);
#pragma unroll
    for (int q = 0; q < 4; q++) {
        int idx = q * 256 + tid;
        int r = idx >> 3, cc = idx & 7;
        asm volatile("cp.async.cg.shared.global [%0], [%1], 16;" ::"r"(dbase + r * 144 + cc * 16),
                     "l"(src + r * 128 + cc * 16));
    }
    asm volatile("cp.async.commit_group;" ::: "memory");
}

__device__ __forceinline__ void pv_build(char* smem, int buf, int jt, const int4* Ac,
                                         __nv_bfloat162 UX, __nv_bfloat162 UX2, int il, int jc) {
    int j0 = jt << 7;
    const uint4* vp = (const uint4*)(g_vp + (j0 >> 1) + (jc << 3));
    uint4 vA = __ldg(vp), vB = __ldg(vp + 1);
    const uint4* wp = (const uint4*)(g_vp2 + (j0 >> 1) + (jc << 3));
    uint4 wA = __ldg(wp), wB = __ldg(wp + 1);
    uint32_t po[8];
    uint32_t m;
#define PV_PAIR(dst, a0v, a1v, vv, ww)                                                   \
    m = __byte_perm((uint32_t)(a0v), (uint32_t)(a1v), 0x5410) * 0x3F80u;                 \
    dst = asu32(__hmul2(__hmax2(__hmul2(UX, asb2(vv)), __hmul2(UX2, asb2(ww))), asb2(m)));
    PV_PAIR(po[0], Ac[0].x, Ac[0].y, vA.x, wA.x)
    PV_PAIR(po[1], Ac[0].z, Ac[0].w, vA.y, wA.y)
    PV_PAIR(po[2], Ac[1].x, Ac[1].y, vA.z, wA.z)
    PV_PAIR(po[3], Ac[1].z, Ac[1].w, vA.w, wA.w)
    PV_PAIR(po[4], Ac[2].x, Ac[2].y, vB.x, wB.x)
    PV_PAIR(po[5], Ac[2].z, Ac[2].w, vB.y, wB.y)
    PV_PAIR(po[6], Ac[3].x, Ac[3].y, vB.z, wB.z)
    PV_PAIR(po[7], Ac[3].z, Ac[3].w, vB.w, wB.w)
#undef PV_PAIR
    char* pdst = smem + OFF_PT + buf * PT_STRIDE + il * 272 + (jc << 5);
    *(uint4*)pdst = make_uint4(po[0], po[1], po[2], po[3]);
    *(uint4*)(pdst + 16) = make_uint4(po[4], po[5], po[6], po[7]);
}

__global__ __launch_bounds__(256) void k_pv(const int* __restrict__ A,
                                            const float* __restrict__ beta,
                                            float* __restrict__ out) {
    extern __shared__ __align__(16) char smem[];
    uint32_t sm = (uint32_t)__cvta_generic_to_shared(smem);
    int tid = threadIdx.x, lane = tid & 31, wid = tid >> 5;
    int i0 = blockIdx.x * 32;
    int mi = (wid >> 2) * 16, nb = (wid & 3) * 16;
    int il = tid >> 3, jc = tid & 7;
    const int4* arow = (const int4*)(A + (long)(i0 + il) * NN) + (jc << 2);
    __nv_bfloat162 UX = asb2(g_up[i0 + il]);
    __nv_bfloat162 UX2 = asb2(g_up2[i0 + il]);

    float acc[2][4], accz[4];
#pragma unroll
    for (int j = 0; j < 4; j++) { acc[0][j] = 0.f; acc[1][j] = 0.f; accz[j] = 0.f; }

    // prologue: gT0, gT1 in flight; build P0; A tile1 into regs
    pv_load_gt(sm, 0, 0, tid);
    pv_load_gt(sm, 1, 128, tid);
    int4 Ac[4];
#pragma unroll
    for (int q = 0; q < 4; q++) Ac[q] = __ldcs(arow + q);
    pv_build(smem, 0, 0, Ac, UX, UX2, il, jc);
#pragma unroll
    for (int q = 0; q < 4; q++) Ac[q] = __ldcs(arow + 32 + q);

    const uint32_t ONES = 0x3F803F80u;
    int g = lane >> 3;
    int r = (lane & 7) + (g & 1) * 8;
    int c = (g >> 1) * 8;

    for (int jt = 0; jt < NJT; jt++) {
        __syncthreads();   // pT[jt&1] built; gT buffer (jt+2)%3 free for refill

        if (jt < NJT - 2) pv_load_gt(sm, (jt + 2) % 3, (jt + 2) << 7, tid);
        if (jt < NJT - 2)
            asm volatile("cp.async.wait_group 2;" ::: "memory");
        else if (jt == NJT - 2)
            asm volatile("cp.async.wait_group 1;" ::: "memory");
        else
            asm volatile("cp.async.wait_group 0;" ::: "memory");

        // mma on current buffers
        const char* pb = smem + OFF_PT + (jt & 1) * PT_STRIDE;
        const char* hb = smem + OFF_GT + (jt % 3) * GT_STRIDE;
#pragma unroll
        for (int ks = 0; ks < 8; ks++) {
            uint32_t a0, a1, a2, a3;
            ldsm4(a0, a1, a2, a3, pb + (mi + r) * 272 + (ks * 16 + c) * 2);
            if ((wid & 3) == 0) mma16816(accz, a0, a1, a2, a3, ONES, ONES);
            uint32_t b0, b1r, b2, b3;
            ldsm4t(b0, b1r, b2, b3, hb + (ks * 16 + r) * 144 + (nb + c) * 2);
            mma16816(acc[0], a0, a1, a2, a3, b0, b1r);
            mma16816(acc[1], a0, a1, a2, a3, b2, b3);
        }

        // build next P tile into the other buffer; prefetch A two ahead
        if (jt < NJT - 1) {
            pv_build(smem, (jt + 1) & 1, jt + 1, Ac, UX, UX2, il, jc);
            if (jt < NJT - 2) {
#pragma unroll
                for (int q = 0; q < 4; q++) Ac[q] = __ldcs(arow + (long)(jt + 2) * 32 + q);
            }
        }
    }

    float* sZ = (float*)(smem + OFF_SZ);
    if (((wid & 3) == 0) && ((lane & 3) == 0)) {
        sZ[mi + (lane >> 2)] = accz[0];
        sZ[mi + 8 + (lane >> 2)] = accz[2];
    }
    __syncthreads();
    int r0 = mi + (lane >> 2);
    float iz0 = 1.f / sZ[r0];
    float iz1 = 1.f / sZ[r0 + 8];
#pragma unroll
    for (int h = 0; h < 2; h++) {
        int cb = nb + h * 8 + (lane & 3) * 2;
        float be0 = beta[cb], be1 = beta[cb + 1];
        out[(i0 + r0) * OUTD + cb] = 1.f / (1.f + expf(-(acc[h][0] * iz0 + be0)));
        out[(i0 + r0) * OUTD + cb + 1] = 1.f / (1.f + expf(-(acc[h][1] * iz0 + be1)));
        out[(i0 + r0 + 8) * OUTD + cb] = 1.f / (1.f + expf(-(acc[h][2] * iz1 + be0)));
        out[(i0 + r0 + 8) * OUTD + cb + 1] = 1.f / (1.f + expf(-(acc[h][3] * iz1 + be1)));
    }
}

// ---------------- launch ----------------
extern "C" void kernel_launch(void* const* d_in, const int* in_sizes, int n_in,
                              void* d_out, int out_size) {
    const float* X = (const float*)d_in[0];
    const int* A = (const int*)d_in[1];
    const float* W1 = (const float*)d_in[2];
    const float* b1 = (const float*)d_in[3];
    const float* a = (const float*)d_in[4];
    const float* Omega = (const float*)d_in[5];
    const float* beta = (const float*)d_in[6];
    float* out = (float*)d_out;

    cudaFuncSetAttribute(k_pv, cudaFuncAttributeMaxDynamicSharedMemorySize, SMEM_PV);

    k_prep<<<IND + 1, 128>>>(W1, b1, a, Omega);
    k_splitX<<<(NN * IND + 255) / 256, 256>>>(X);
    k_sg<<<NN / 64, 256>>>();
    k_max<<<NN / 1024, 1024>>>();
    k_uvp<<<NN / 256, 256>>>();
    k_pv<<<NN / 32, 256, SMEM_PV>>>(A, beta, out);
}

// round 12
// speedup vs baseline: 7.1636x; 1.0500x over previous
#include <cuda_runtime.h>
#include <cuda_bf16.h>
#include <cstdint>

#define NN 8192
#define IND 512
#define HID 256
#define OUTD 64
#define NC 80       // Wt cols: G[0:64], s1=64, s2=65, pad to 80
#define NJT 64      // j-tiles of 128 per CTA

// ---------------- scratch ----------------
__device__ __nv_bfloat16 g_Wt[1024 * NC];   // split W-tilde, chunk-interleaved rows
__device__ float g_bc[66];
__device__ __nv_bfloat16 g_Gb[NN * OUTD];   // G = H1@Omega + b, bf16 row-major (L2-resident)
__device__ float g_s1[NN], g_s2[NN];
__device__ uint32_t g_up[NN], g_up2[NN];    // u_i / u2_i duplicated bf16x2
__device__ uint32_t g_vp[NN / 2], g_vp2[NN / 2];

// ---------------- mma helpers ----------------
__device__ __forceinline__ void ldsm4(uint32_t& r0, uint32_t& r1, uint32_t& r2, uint32_t& r3,
                                      const void* p) {
    uint32_t ad = (uint32_t)__cvta_generic_to_shared(p);
    asm volatile("ldmatrix.sync.aligned.m8n8.x4.shared.b16 {%0,%1,%2,%3}, [%4];"
                 : "=r"(r0), "=r"(r1), "=r"(r2), "=r"(r3) : "r"(ad));
}
__device__ __forceinline__ void ldsm4t(uint32_t& r0, uint32_t& r1, uint32_t& r2, uint32_t& r3,
                                       const void* p) {
    uint32_t ad = (uint32_t)__cvta_generic_to_shared(p);
    asm volatile("ldmatrix.sync.aligned.m8n8.x4.trans.shared.b16 {%0,%1,%2,%3}, [%4];"
                 : "=r"(r0), "=r"(r1), "=r"(r2), "=r"(r3) : "r"(ad));
}
__device__ __forceinline__ void mma16816(float* c, uint32_t a0, uint32_t a1, uint32_t a2,
                                         uint32_t a3, uint32_t b0, uint32_t b1) {
    asm volatile(
        "mma.sync.aligned.m16n8k16.row.col.f32.bf16.bf16.f32 "
        "{%0,%1,%2,%3}, {%4,%5,%6,%7}, {%8,%9}, {%0,%1,%2,%3};"
        : "+f"(c[0]), "+f"(c[1]), "+f"(c[2]), "+f"(c[3])
        : "r"(a0), "r"(a1), "r"(a2), "r"(a3), "r"(b0), "r"(b1));
}
__device__ __forceinline__ __nv_bfloat162 asb2(uint32_t x) {
    return *reinterpret_cast<__nv_bfloat162*>(&x);
}
__device__ __forceinline__ uint32_t asu32(__nv_bfloat162 x) {
    return *reinterpret_cast<uint32_t*>(&x);
}

// ---------------- k_prep: W~ = [W1@Omega | W1@a1 | W1@a2], chunk-interleaved split rows ----
// For fp32 col k: chunk = k>>5, pos = k&31. hi row = 64*chunk + pos, lo row = hi + 32.
__global__ void k_prep(const float* __restrict__ W1, const float* __restrict__ b1,
                       const float* __restrict__ a, const float* __restrict__ Omega) {
    __shared__ float wrow[HID];
    int blk = blockIdx.x;   // 0..511: W1 row; 512: b1
    int tid = threadIdx.x;
    const float* src = (blk < IND) ? (W1 + blk * HID) : b1;
    for (int k = tid; k < HID; k += 128) wrow[k] = src[k];
    __syncthreads();
    if (tid >= NC) return;
    float val = 0.f;
    if (tid < 64) {
        for (int k = 0; k < HID; k++) val += wrow[k] * Omega[k * OUTD + tid];
    } else if (tid == 64) {
        for (int k = 0; k < HID; k++) val += wrow[k] * a[k];
    } else if (tid == 65) {
        for (int k = 0; k < HID; k++) val += wrow[k] * a[HID + k];
    }
    if (blk < IND) {
        __nv_bfloat16 hi = __float2bfloat16(val);
        float lo = val - __bfloat162float(hi);
        int rhi = ((blk >> 5) << 6) + (blk & 31);
        g_Wt[rhi * NC + tid] = hi;
        g_Wt[(rhi + 32) * NC + tid] = __float2bfloat16(lo);
    } else if (tid < 66) {
        g_bc[tid] = val;
    }
}

// ---------------- k_sg: [G | s1 | s2] = split(X) @ Wt, inline fp32->bf16 hi/lo split ------
__global__ __launch_bounds__(256) void k_sg(const float* __restrict__ X) {
    __shared__ __align__(16) __nv_bfloat16 aT[64][72];   // 64 rows x (32 hi | 32 lo)
    __shared__ __align__(16) __nv_bfloat16 bT[64][88];
    int tid = threadIdx.x, lane = tid & 31, w = tid >> 5;
    int m0 = blockIdx.x * 64;
    int mi = (w >> 1) * 16;
    int cw = w & 1;   // 0: nt 0..2 (cols 0-47), 1: nt 3..4 (cols 48-79)
    float acc[6][4];
#pragma unroll
    for (int i = 0; i < 6; i++)
#pragma unroll
        for (int j = 0; j < 4; j++) acc[i][j] = 0.f;

    for (int ch = 0; ch < 16; ch++) {
        // A tile: X[64 rows][32 fp32 cols] -> hi cols 0-31, lo cols 32-63
#pragma unroll
        for (int q = 0; q < 2; q++) {
            int idx = q * 256 + tid;          // 512 float4
            int rr = idx >> 3, c4 = (idx & 7) * 4;
            float4 xv = *(const float4*)&X[(m0 + rr) * IND + ch * 32 + c4];
            __nv_bfloat162 h0 = __floats2bfloat162_rn(xv.x, xv.y);
            __nv_bfloat162 h1 = __floats2bfloat162_rn(xv.z, xv.w);
            __nv_bfloat162 l0 = __floats2bfloat162_rn(xv.x - __bfloat162float(__low2bfloat16(h0)),
                                                      xv.y - __bfloat162float(__high2bfloat16(h0)));
            __nv_bfloat162 l1 = __floats2bfloat162_rn(xv.z - __bfloat162float(__low2bfloat16(h1)),
                                                      xv.w - __bfloat162float(__high2bfloat16(h1)));
            *(uint2*)&aT[rr][c4] = make_uint2(asu32(h0), asu32(h1));
            *(uint2*)&aT[rr][32 + c4] = make_uint2(asu32(l0), asu32(l1));
        }
        // B tile: Wt rows [64ch, 64ch+64)
#pragma unroll
        for (int q = 0; q < 3; q++) {
            int idx = q * 256 + tid;
            if (idx < 640) {
                int rr = idx / 10, cc = idx % 10;
                *(uint4*)&bT[rr][cc * 8] = *(const uint4*)&g_Wt[(ch * 64 + rr) * NC + cc * 8];
            }
        }
        __syncthreads();
        int g = lane >> 3;
        int r = (lane & 7) + (g & 1) * 8;
        int c = (g >> 1) * 8;
#pragma unroll
        for (int ks = 0; ks < 64; ks += 16) {
            uint32_t a0, a1, a2, a3;
            ldsm4(a0, a1, a2, a3, &aT[mi + r][ks + c]);
            if (cw == 0) {
#pragma unroll
                for (int nt = 0; nt < 3; nt++) {
                    uint32_t b0, b1r, b2, b3;
                    ldsm4t(b0, b1r, b2, b3, &bT[ks + r][nt * 16 + c]);
                    mma16816(acc[nt * 2], a0, a1, a2, a3, b0, b1r);
                    mma16816(acc[nt * 2 + 1], a0, a1, a2, a3, b2, b3);
                }
            } else {
#pragma unroll
                for (int nt2 = 0; nt2 < 2; nt2++) {
                    uint32_t b0, b1r, b2, b3;
                    ldsm4t(b0, b1r, b2, b3, &bT[ks + r][(nt2 + 3) * 16 + c]);
                    mma16816(acc[nt2 * 2], a0, a1, a2, a3, b0, b1r);
                    mma16816(acc[nt2 * 2 + 1], a0, a1, a2, a3, b2, b3);
                }
            }
        }
        __syncthreads();
    }
    int r0 = m0 + mi + (lane >> 2);
    if (cw == 0) {
#pragma unroll
        for (int nt = 0; nt < 3; nt++)
#pragma unroll
            for (int h = 0; h < 2; h++) {
                int j = nt * 2 + h;
                int cb = nt * 16 + h * 8 + (lane & 3) * 2;
                float b0v = g_bc[cb], b1v = g_bc[cb + 1];
                __nv_bfloat162 p0 = __floats2bfloat162_rn(acc[j][0] + b0v, acc[j][1] + b1v);
                __nv_bfloat162 p1 = __floats2bfloat162_rn(acc[j][2] + b0v, acc[j][3] + b1v);
                *(uint32_t*)&g_Gb[r0 * OUTD + cb] = asu32(p0);
                *(uint32_t*)&g_Gb[(r0 + 8) * OUTD + cb] = asu32(p1);
            }
    } else {
#pragma unroll
        for (int h = 0; h < 2; h++) {
            int cb = 48 + h * 8 + (lane & 3) * 2;
            float b0v = g_bc[cb], b1v = g_bc[cb + 1];
            __nv_bfloat162 p0 = __floats2bfloat162_rn(acc[h][0] + b0v, acc[h][1] + b1v);
            __nv_bfloat162 p1 = __floats2bfloat162_rn(acc[h][2] + b0v, acc[h][3] + b1v);
            *(uint32_t*)&g_Gb[r0 * OUTD + cb] = asu32(p0);
            *(uint32_t*)&g_Gb[(r0 + 8) * OUTD + cb] = asu32(p1);
        }
        if ((lane & 3) == 0) {
            g_s1[r0] = acc[2][0] + g_bc[64];
            g_s2[r0] = acc[2][1] + g_bc[65];
            g_s1[r0 + 8] = acc[2][2] + g_bc[64];
            g_s2[r0 + 8] = acc[2][3] + g_bc[65];
        }
    }
}

// ---------------- k_maxuv: single-CTA max(s2) + u/v factor packing ----------------
__global__ __launch_bounds__(1024) void k_maxuv() {
    __shared__ float red[32];
    int tid = threadIdx.x, lane = tid & 31;
    float m = -1e30f;
    for (int i = tid; i < NN; i += 1024) m = fmaxf(m, g_s2[i]);
#pragma unroll
    for (int o = 16; o; o >>= 1) m = fmaxf(m, __shfl_xor_sync(0xffffffffu, m, o));
    if (lane == 0) red[tid >> 5] = m;
    __syncthreads();
    if (tid < 32) {
        float x = red[tid];
#pragma unroll
        for (int o = 16; o; o >>= 1) x = fmaxf(x, __shfl_xor_sync(0xffffffffu, x, o));
        if (tid == 0) red[0] = x;
    }
    __syncthreads();
    float M = red[0];
    for (int i = tid; i < NN; i += 1024) {
        float s1 = g_s1[i], s2 = g_s2[i];
        float t = s1 + M;
        float c = t > 0.f ? t : 0.2f * t;   // valid softmax shift (leaky_relu monotone)
        uint32_t ub = (uint32_t)__bfloat16_as_ushort(__float2bfloat16(expf(s1 - c)));
        g_up[i] = ub | (ub << 16);
        uint32_t u2b = (uint32_t)__bfloat16_as_ushort(__float2bfloat16(expf(0.2f * s1 - c)));
        g_up2[i] = u2b | (u2b << 16);
        if (i < NN / 2) {
            float sa = g_s2[2 * i], sb = g_s2[2 * i + 1];
            uint32_t v0 = (uint32_t)__bfloat16_as_ushort(__float2bfloat16(expf(sa)));
            uint32_t v1 = (uint32_t)__bfloat16_as_ushort(__float2bfloat16(expf(sb)));
            g_vp[i] = v0 | (v1 << 16);
            uint32_t w0 = (uint32_t)__bfloat16_as_ushort(__float2bfloat16(expf(0.2f * sa)));
            uint32_t w1 = (uint32_t)__bfloat16_as_ushort(__float2bfloat16(expf(0.2f * sb)));
            g_vp2[i] = w0 | (w1 << 16);
        }
    }
}

// ---------------- k_pv: out = sigmoid((P@G)/Z + beta), pipelined mma.sync ----------------
// smem: gT[3][128][72] bf16 (cp.async triple buffer), pT[2][32][136] bf16, sZ[32]
#define GT_STRIDE 18432                     // 128*144 B
#define OFF_GT 0                            // 3 * 18432 = 55296
#define OFF_PT 55296                        // 2 * 8704 = 17408
#define PT_STRIDE 8704                      // 32*272 B
#define OFF_SZ 72704
#define SMEM_PV 72832

__device__ __forceinline__ void pv_load_gt(uint32_t sm, int buf, int j0, int tid) {
    uint32_t dbase = sm + OFF_GT + buf * GT_STRIDE;
    const char* src = (const char*)(g_Gb + (size_t)j0 * OUTD);
#pragma unroll
    for (int q = 0; q < 4; q++) {
        int idx = q * 256 + tid;
        int r = idx >> 3, cc = idx & 7;
        asm volatile("cp.async.cg.shared.global [%0], [%1], 16;" ::"r"(dbase + r * 144 + cc * 16),
                     "l"(src + r * 128 + cc * 16));
    }
    asm volatile("cp.async.commit_group;" ::: "memory");
}

__device__ __forceinline__ void pv_build(char* smem, int buf, int jt, const int4* Ac,
                                         __nv_bfloat162 UX, __nv_bfloat162 UX2, int il, int jc) {
    int j0 = jt << 7;
    const uint4* vp = (const uint4*)(g_vp + (j0 >> 1) + (jc << 3));
    uint4 vA = __ldg(vp), vB = __ldg(vp + 1);
    const uint4* wp = (const uint4*)(g_vp2 + (j0 >> 1) + (jc << 3));
    uint4 wA = __ldg(wp), wB = __ldg(wp + 1);
    uint32_t po[8];
    uint32_t m;
#define PV_PAIR(dst, a0v, a1v, vv, ww)                                                   \
    m = __byte_perm((uint32_t)(a0v), (uint32_t)(a1v), 0x5410) * 0x3F80u;                 \
    dst = asu32(__hmul2(__hmax2(__hmul2(UX, asb2(vv)), __hmul2(UX2, asb2(ww))), asb2(m)));
    PV_PAIR(po[0], Ac[0].x, Ac[0].y, vA.x, wA.x)
    PV_PAIR(po[1], Ac[0].z, Ac[0].w, vA.y, wA.y)
    PV_PAIR(po[2], Ac[1].x, Ac[1].y, vA.z, wA.z)
    PV_PAIR(po[3], Ac[1].z, Ac[1].w, vA.w, wA.w)
    PV_PAIR(po[4], Ac[2].x, Ac[2].y, vB.x, wB.x)
    PV_PAIR(po[5], Ac[2].z, Ac[2].w, vB.y, wB.y)
    PV_PAIR(po[6], Ac[3].x, Ac[3].y, vB.z, wB.z)
    PV_PAIR(po[7], Ac[3].z, Ac[3].w, vB.w, wB.w)
#undef PV_PAIR
    char* pdst = smem + OFF_PT + buf * PT_STRIDE + il * 272 + (jc << 5);
    *(uint4*)pdst = make_uint4(po[0], po[1], po[2], po[3]);
    *(uint4*)(pdst + 16) = make_uint4(po[4], po[5], po[6], po[7]);
}

__global__ __launch_bounds__(256) void k_pv(const int* __restrict__ A,
                                            const float* __restrict__ beta,
                                            float* __restrict__ out) {
    extern __shared__ __align__(16) char smem[];
    uint32_t sm = (uint32_t)__cvta_generic_to_shared(smem);
    int tid = threadIdx.x, lane = tid & 31, wid = tid >> 5;
    int i0 = blockIdx.x * 32;
    int mi = (wid >> 2) * 16, nb = (wid & 3) * 16;
    int il = tid >> 3, jc = tid & 7;
    const int4* arow = (const int4*)(A + (long)(i0 + il) * NN) + (jc << 2);
    __nv_bfloat162 UX = asb2(g_up[i0 + il]);
    __nv_bfloat162 UX2 = asb2(g_up2[i0 + il]);

    float acc[2][4], accz[4];
#pragma unroll
    for (int j = 0; j < 4; j++) { acc[0][j] = 0.f; acc[1][j] = 0.f; accz[j] = 0.f; }

    // prologue: gT0, gT1 in flight; build P0; A tile1 into regs
    pv_load_gt(sm, 0, 0, tid);
    pv_load_gt(sm, 1, 128, tid);
    int4 Ac[4];
#pragma unroll
    for (int q = 0; q < 4; q++) Ac[q] = __ldcs(arow + q);
    pv_build(smem, 0, 0, Ac, UX, UX2, il, jc);
#pragma unroll
    for (int q = 0; q < 4; q++) Ac[q] = __ldcs(arow + 32 + q);

    const uint32_t ONES = 0x3F803F80u;
    int g = lane >> 3;
    int r = (lane & 7) + (g & 1) * 8;
    int c = (g >> 1) * 8;

    for (int jt = 0; jt < NJT; jt++) {
        __syncthreads();   // pT[jt&1] built; gT buffer (jt+2)%3 free for refill

        if (jt < NJT - 2) pv_load_gt(sm, (jt + 2) % 3, (jt + 2) << 7, tid);
        if (jt < NJT - 2)
            asm volatile("cp.async.wait_group 2;" ::: "memory");
        else if (jt == NJT - 2)
            asm volatile("cp.async.wait_group 1;" ::: "memory");
        else
            asm volatile("cp.async.wait_group 0;" ::: "memory");

        // mma on current buffers
        const char* pb = smem + OFF_PT + (jt & 1) * PT_STRIDE;
        const char* hb = smem + OFF_GT + (jt % 3) * GT_STRIDE;
#pragma unroll
        for (int ks = 0; ks < 8; ks++) {
            uint32_t a0, a1, a2, a3;
            ldsm4(a0, a1, a2, a3, pb + (mi + r) * 272 + (ks * 16 + c) * 2);
            if ((wid & 3) == 0) mma16816(accz, a0, a1, a2, a3, ONES, ONES);
            uint32_t b0, b1r, b2, b3;
            ldsm4t(b0, b1r, b2, b3, hb + (ks * 16 + r) * 144 + (nb + c) * 2);
            mma16816(acc[0], a0, a1, a2, a3, b0, b1r);
            mma16816(acc[1], a0, a1, a2, a3, b2, b3);
        }

        // build next P tile into the other buffer; prefetch A two ahead
        if (jt < NJT - 1) {
            pv_build(smem, (jt + 1) & 1, jt + 1, Ac, UX, UX2, il, jc);
            if (jt < NJT - 2) {
#pragma unroll
                for (int q = 0; q < 4; q++) Ac[q] = __ldcs(arow + (long)(jt + 2) * 32 + q);
            }
        }
    }

    float* sZ = (float*)(smem + OFF_SZ);
    if (((wid & 3) == 0) && ((lane & 3) == 0)) {
        sZ[mi + (lane >> 2)] = accz[0];
        sZ[mi + 8 + (lane >> 2)] = accz[2];
    }
    __syncthreads();
    int r0 = mi + (lane >> 2);
    float iz0 = 1.f / sZ[r0];
    float iz1 = 1.f / sZ[r0 + 8];
#pragma unroll
    for (int h = 0; h < 2; h++) {
        int cb = nb + h * 8 + (lane & 3) * 2;
        float be0 = beta[cb], be1 = beta[cb + 1];
        out[(i0 + r0) * OUTD + cb] = 1.f / (1.f + expf(-(acc[h][0] * iz0 + be0)));
        out[(i0 + r0) * OUTD + cb + 1] = 1.f / (1.f + expf(-(acc[h][1] * iz0 + be1)));
        out[(i0 + r0 + 8) * OUTD + cb] = 1.f / (1.f + expf(-(acc[h][2] * iz1 + be0)));
        out[(i0 + r0 + 8) * OUTD + cb + 1] = 1.f / (1.f + expf(-(acc[h][3] * iz1 + be1)));
    }
}

// ---------------- launch: 4 kernels, k_pv at profiled index 3 ----------------
extern "C" void kernel_launch(void* const* d_in, const int* in_sizes, int n_in,
                              void* d_out, int out_size) {
    const float* X = (const float*)d_in[0];
    const int* A = (const int*)d_in[1];
    const float* W1 = (const float*)d_in[2];
    const float* b1 = (const float*)d_in[3];
    const float* a = (const float*)d_in[4];
    const float* Omega = (const float*)d_in[5];
    const float* beta = (const float*)d_in[6];
    float* out = (float*)d_out;

    cudaFuncSetAttribute(k_pv, cudaFuncAttributeMaxDynamicSharedMemorySize, SMEM_PV);

    k_prep<<<IND + 1, 128>>>(W1, b1, a, Omega);
    k_sg<<<NN / 64, 256>>>(X);
    k_maxuv<<<1, 1024>>>();
    k_pv<<<NN / 32, 256, SMEM_PV>>>(A, beta, out);
}

// round 13
// speedup vs baseline: 7.9140x; 1.1048x over previous
#include <cuda_runtime.h>
#include <cuda_bf16.h>
#include <cstdint>

#define NN 8192
#define IND 512
#define HID 256
#define OUTD 64
#define NC 80       // Wt cols: G[0:64], s1=64, s2=65, pad to 80
#define NJT 32      // j-tiles of 128 per CTA (split-j: 2 CTAs per i-tile)
#define PROW 68     // partial row stride (floats): 64 cols + Z + pad

// ---------------- scratch ----------------
__device__ __nv_bfloat16 g_Wt[1024 * NC];   // split W-tilde, chunk-interleaved rows
__device__ float g_bc[66];
__device__ __nv_bfloat16 g_Gb[NN * OUTD];   // G = H1@Omega + b, bf16 row-major (L2-resident)
__device__ float g_s1[NN], g_s2[NN];
__device__ uint32_t g_up[NN], g_up2[NN];    // u_i / u2_i duplicated bf16x2
__device__ uint32_t g_vp[NN / 2], g_vp2[NN / 2];
__device__ float g_Part[2 * NN * PROW];     // split-j partials [jhalf][row][68]

// ---------------- mma helpers ----------------
__device__ __forceinline__ void ldsm4(uint32_t& r0, uint32_t& r1, uint32_t& r2, uint32_t& r3,
                                      const void* p) {
    uint32_t ad = (uint32_t)__cvta_generic_to_shared(p);
    asm volatile("ldmatrix.sync.aligned.m8n8.x4.shared.b16 {%0,%1,%2,%3}, [%4];"
                 : "=r"(r0), "=r"(r1), "=r"(r2), "=r"(r3) : "r"(ad));
}
__device__ __forceinline__ void ldsm4t(uint32_t& r0, uint32_t& r1, uint32_t& r2, uint32_t& r3,
                                       const void* p) {
    uint32_t ad = (uint32_t)__cvta_generic_to_shared(p);
    asm volatile("ldmatrix.sync.aligned.m8n8.x4.trans.shared.b16 {%0,%1,%2,%3}, [%4];"
                 : "=r"(r0), "=r"(r1), "=r"(r2), "=r"(r3) : "r"(ad));
}
__device__ __forceinline__ void mma16816(float* c, uint32_t a0, uint32_t a1, uint32_t a2,
                                         uint32_t a3, uint32_t b0, uint32_t b1) {
    asm volatile(
        "mma.sync.aligned.m16n8k16.row.col.f32.bf16.bf16.f32 "
        "{%0,%1,%2,%3}, {%4,%5,%6,%7}, {%8,%9}, {%0,%1,%2,%3};"
        : "+f"(c[0]), "+f"(c[1]), "+f"(c[2]), "+f"(c[3])
        : "r"(a0), "r"(a1), "r"(a2), "r"(a3), "r"(b0), "r"(b1));
}
__device__ __forceinline__ __nv_bfloat162 asb2(uint32_t x) {
    return *reinterpret_cast<__nv_bfloat162*>(&x);
}
__device__ __forceinline__ uint32_t asu32(__nv_bfloat162 x) {
    return *reinterpret_cast<uint32_t*>(&x);
}

// ---------------- k_prep: W~ = [W1@Omega | W1@a1 | W1@a2], chunk-interleaved split rows ----
__global__ void k_prep(const float* __restrict__ W1, const float* __restrict__ b1,
                       const float* __restrict__ a, const float* __restrict__ Omega) {
    __shared__ float wrow[HID];
    int blk = blockIdx.x;   // 0..511: W1 row; 512: b1
    int tid = threadIdx.x;
    const float* src = (blk < IND) ? (W1 + blk * HID) : b1;
    for (int k = tid; k < HID; k += 128) wrow[k] = src[k];
    __syncthreads();
    if (tid >= NC) return;
    float val = 0.f;
    if (tid < 64) {
        for (int k = 0; k < HID; k++) val += wrow[k] * Omega[k * OUTD + tid];
    } else if (tid == 64) {
        for (int k = 0; k < HID; k++) val += wrow[k] * a[k];
    } else if (tid == 65) {
        for (int k = 0; k < HID; k++) val += wrow[k] * a[HID + k];
    }
    if (blk < IND) {
        __nv_bfloat16 hi = __float2bfloat16(val);
        float lo = val - __bfloat162float(hi);
        int rhi = ((blk >> 5) << 6) + (blk & 31);
        g_Wt[rhi * NC + tid] = hi;
        g_Wt[(rhi + 32) * NC + tid] = __float2bfloat16(lo);
    } else if (tid < 66) {
        g_bc[tid] = val;
    }
}

// ---------------- k_sg: [G | s1 | s2] = split(X) @ Wt, inline fp32->bf16 hi/lo split ------
__global__ __launch_bounds__(256) void k_sg(const float* __restrict__ X) {
    __shared__ __align__(16) __nv_bfloat16 aT[64][72];   // 64 rows x (32 hi | 32 lo)
    __shared__ __align__(16) __nv_bfloat16 bT[64][88];
    int tid = threadIdx.x, lane = tid & 31, w = tid >> 5;
    int m0 = blockIdx.x * 64;
    int mi = (w >> 1) * 16;
    int cw = w & 1;   // 0: nt 0..2 (cols 0-47), 1: nt 3..4 (cols 48-79)
    float acc[6][4];
#pragma unroll
    for (int i = 0; i < 6; i++)
#pragma unroll
        for (int j = 0; j < 4; j++) acc[i][j] = 0.f;

    for (int ch = 0; ch < 16; ch++) {
#pragma unroll
        for (int q = 0; q < 2; q++) {
            int idx = q * 256 + tid;          // 512 float4
            int rr = idx >> 3, c4 = (idx & 7) * 4;
            float4 xv = *(const float4*)&X[(m0 + rr) * IND + ch * 32 + c4];
            __nv_bfloat162 h0 = __floats2bfloat162_rn(xv.x, xv.y);
            __nv_bfloat162 h1 = __floats2bfloat162_rn(xv.z, xv.w);
            __nv_bfloat162 l0 = __floats2bfloat162_rn(xv.x - __bfloat162float(__low2bfloat16(h0)),
                                                      xv.y - __bfloat162float(__high2bfloat16(h0)));
            __nv_bfloat162 l1 = __floats2bfloat162_rn(xv.z - __bfloat162float(__low2bfloat16(h1)),
                                                      xv.w - __bfloat162float(__high2bfloat16(h1)));
            *(uint2*)&aT[rr][c4] = make_uint2(asu32(h0), asu32(h1));
            *(uint2*)&aT[rr][32 + c4] = make_uint2(asu32(l0), asu32(l1));
        }
#pragma unroll
        for (int q = 0; q < 3; q++) {
            int idx = q * 256 + tid;
            if (idx < 640) {
                int rr = idx / 10, cc = idx % 10;
                *(uint4*)&bT[rr][cc * 8] = *(const uint4*)&g_Wt[(ch * 64 + rr) * NC + cc * 8];
            }
        }
        __syncthreads();
        int g = lane >> 3;
        int r = (lane & 7) + (g & 1) * 8;
        int c = (g >> 1) * 8;
#pragma unroll
        for (int ks = 0; ks < 64; ks += 16) {
            uint32_t a0, a1, a2, a3;
            ldsm4(a0, a1, a2, a3, &aT[mi + r][ks + c]);
            if (cw == 0) {
#pragma unroll
                for (int nt = 0; nt < 3; nt++) {
                    uint32_t b0, b1r, b2, b3;
                    ldsm4t(b0, b1r, b2, b3, &bT[ks + r][nt * 16 + c]);
                    mma16816(acc[nt * 2], a0, a1, a2, a3, b0, b1r);
                    mma16816(acc[nt * 2 + 1], a0, a1, a2, a3, b2, b3);
                }
            } else {
#pragma unroll
                for (int nt2 = 0; nt2 < 2; nt2++) {
                    uint32_t b0, b1r, b2, b3;
                    ldsm4t(b0, b1r, b2, b3, &bT[ks + r][(nt2 + 3) * 16 + c]);
                    mma16816(acc[nt2 * 2], a0, a1, a2, a3, b0, b1r);
                    mma16816(acc[nt2 * 2 + 1], a0, a1, a2, a3, b2, b3);
                }
            }
        }
        __syncthreads();
    }
    int r0 = m0 + mi + (lane >> 2);
    if (cw == 0) {
#pragma unroll
        for (int nt = 0; nt < 3; nt++)
#pragma unroll
            for (int h = 0; h < 2; h++) {
                int j = nt * 2 + h;
                int cb = nt * 16 + h * 8 + (lane & 3) * 2;
                float b0v = g_bc[cb], b1v = g_bc[cb + 1];
                __nv_bfloat162 p0 = __floats2bfloat162_rn(acc[j][0] + b0v, acc[j][1] + b1v);
                __nv_bfloat162 p1 = __floats2bfloat162_rn(acc[j][2] + b0v, acc[j][3] + b1v);
                *(uint32_t*)&g_Gb[r0 * OUTD + cb] = asu32(p0);
                *(uint32_t*)&g_Gb[(r0 + 8) * OUTD + cb] = asu32(p1);
            }
    } else {
#pragma unroll
        for (int h = 0; h < 2; h++) {
            int cb = 48 + h * 8 + (lane & 3) * 2;
            float b0v = g_bc[cb], b1v = g_bc[cb + 1];
            __nv_bfloat162 p0 = __floats2bfloat162_rn(acc[h][0] + b0v, acc[h][1] + b1v);
            __nv_bfloat162 p1 = __floats2bfloat162_rn(acc[h][2] + b0v, acc[h][3] + b1v);
            *(uint32_t*)&g_Gb[r0 * OUTD + cb] = asu32(p0);
            *(uint32_t*)&g_Gb[(r0 + 8) * OUTD + cb] = asu32(p1);
        }
        if ((lane & 3) == 0) {
            g_s1[r0] = acc[2][0] + g_bc[64];
            g_s2[r0] = acc[2][1] + g_bc[65];
            g_s1[r0 + 8] = acc[2][2] + g_bc[64];
            g_s2[r0 + 8] = acc[2][3] + g_bc[65];
        }
    }
}

// ---------------- k_maxuv: single-CTA max(s2) + u/v factor packing ----------------
__global__ __launch_bounds__(1024) void k_maxuv() {
    __shared__ float red[32];
    int tid = threadIdx.x, lane = tid & 31;
    float m = -1e30f;
    for (int i = tid; i < NN; i += 1024) m = fmaxf(m, g_s2[i]);
#pragma unroll
    for (int o = 16; o; o >>= 1) m = fmaxf(m, __shfl_xor_sync(0xffffffffu, m, o));
    if (lane == 0) red[tid >> 5] = m;
    __syncthreads();
    if (tid < 32) {
        float x = red[tid];
#pragma unroll
        for (int o = 16; o; o >>= 1) x = fmaxf(x, __shfl_xor_sync(0xffffffffu, x, o));
        if (tid == 0) red[0] = x;
    }
    __syncthreads();
    float M = red[0];
    for (int i = tid; i < NN; i += 1024) {
        float s1 = g_s1[i], s2 = g_s2[i];
        float t = s1 + M;
        float c = t > 0.f ? t : 0.2f * t;   // valid softmax shift (leaky_relu monotone)
        uint32_t ub = (uint32_t)__bfloat16_as_ushort(__float2bfloat16(expf(s1 - c)));
        g_up[i] = ub | (ub << 16);
        uint32_t u2b = (uint32_t)__bfloat16_as_ushort(__float2bfloat16(expf(0.2f * s1 - c)));
        g_up2[i] = u2b | (u2b << 16);
        if (i < NN / 2) {
            float sa = g_s2[2 * i], sb = g_s2[2 * i + 1];
            uint32_t v0 = (uint32_t)__bfloat16_as_ushort(__float2bfloat16(expf(sa)));
            uint32_t v1 = (uint32_t)__bfloat16_as_ushort(__float2bfloat16(expf(sb)));
            g_vp[i] = v0 | (v1 << 16);
            uint32_t w0 = (uint32_t)__bfloat16_as_ushort(__float2bfloat16(expf(0.2f * sa)));
            uint32_t w1 = (uint32_t)__bfloat16_as_ushort(__float2bfloat16(expf(0.2f * sb)));
            g_vp2[i] = w0 | (w1 << 16);
        }
    }
}

// ---------------- k_pv: partials = P@[G|1] (split-j, 512 CTAs, 4/SM) ----------------
// smem: gT[2][128][72] bf16 (cp.async double buffer), pT[2][32][136] bf16
#define GT_STRIDE 18432                     // 128*144 B
#define OFF_GT 0                            // 2 * 18432 = 36864
#define OFF_PT 36864                        // 2 * 8704 = 17408
#define PT_STRIDE 8704                      // 32*272 B
#define SMEM_PV 54272

__device__ __forceinline__ void pv_load_gt(uint32_t sm, int buf, int j0, int tid) {
    uint32_t dbase = sm + OFF_GT + buf * GT_STRIDE;
    const char* src = (const char*)(g_Gb + (size_t)j0 * OUTD);
#pragma unroll
    for (int q = 0; q < 4; q++) {
        int idx = q * 256 + tid;
        int r = idx >> 3, cc = idx & 7;
        asm volatile("cp.async.cg.shared.global [%0], [%1], 16;" ::"r"(dbase + r * 144 + cc * 16),
                     "l"(src + r * 128 + cc * 16));
    }
    asm volatile("cp.async.commit_group;" ::: "memory");
}

__device__ __forceinline__ void pv_build(char* smem, int buf, int j0, const int4* Ac,
                                         __nv_bfloat162 UX, __nv_bfloat162 UX2, int il, int jc) {
    const uint4* vp = (const uint4*)(g_vp + (j0 >> 1) + (jc << 3));
    uint4 vA = __ldg(vp), vB = __ldg(vp + 1);
    const uint4* wp = (const uint4*)(g_vp2 + (j0 >> 1) + (jc << 3));
    uint4 wA = __ldg(wp), wB = __ldg(wp + 1);
    uint32_t po[8];
    uint32_t m;
#define PV_PAIR(dst, a0v, a1v, vv, ww)                                                   \
    m = __byte_perm((uint32_t)(a0v), (uint32_t)(a1v), 0x5410) * 0x3F80u;                 \
    dst = asu32(__hmul2(__hmax2(__hmul2(UX, asb2(vv)), __hmul2(UX2, asb2(ww))), asb2(m)));
    PV_PAIR(po[0], Ac[0].x, Ac[0].y, vA.x, wA.x)
    PV_PAIR(po[1], Ac[0].z, Ac[0].w, vA.y, wA.y)
    PV_PAIR(po[2], Ac[1].x, Ac[1].y, vA.z, wA.z)
    PV_PAIR(po[3], Ac[1].z, Ac[1].w, vA.w, wA.w)
    PV_PAIR(po[4], Ac[2].x, Ac[2].y, vB.x, wB.x)
    PV_PAIR(po[5], Ac[2].z, Ac[2].w, vB.y, wB.y)
    PV_PAIR(po[6], Ac[3].x, Ac[3].y, vB.z, wB.z)
    PV_PAIR(po[7], Ac[3].z, Ac[3].w, vB.w, wB.w)
#undef PV_PAIR
    char* pdst = smem + OFF_PT + buf * PT_STRIDE + il * 272 + (jc << 5);
    *(uint4*)pdst = make_uint4(po[0], po[1], po[2], po[3]);
    *(uint4*)(pdst + 16) = make_uint4(po[4], po[5], po[6], po[7]);
}

__global__ __launch_bounds__(256, 4) void k_pv(const int* __restrict__ A) {
    extern __shared__ __align__(16) char smem[];
    uint32_t sm = (uint32_t)__cvta_generic_to_shared(smem);
    int tid = threadIdx.x, lane = tid & 31, wid = tid >> 5;
    int i0 = (blockIdx.x >> 1) * 32;
    int jhalf = blockIdx.x & 1;
    int jbase = jhalf * 4096;
    int mi = (wid >> 2) * 16, nb = (wid & 3) * 16;
    int il = tid >> 3, jc = tid & 7;
    const int4* arow = (const int4*)(A + (long)(i0 + il) * NN + jbase) + (jc << 2);
    __nv_bfloat162 UX = asb2(g_up[i0 + il]);
    __nv_bfloat162 UX2 = asb2(g_up2[i0 + il]);

    float acc[2][4], accz[4];
#pragma unroll
    for (int j = 0; j < 4; j++) { acc[0][j] = 0.f; acc[1][j] = 0.f; accz[j] = 0.f; }

    // prologue: gT0 in flight; build P0; A tile 1 into regs
    pv_load_gt(sm, 0, jbase, tid);
    int4 Ac[4];
#pragma unroll
    for (int q = 0; q < 4; q++) Ac[q] = __ldcs(arow + q);
    pv_build(smem, 0, jbase, Ac, UX, UX2, il, jc);
#pragma unroll
    for (int q = 0; q < 4; q++) Ac[q] = __ldcs(arow + 32 + q);

    const uint32_t ONES = 0x3F803F80u;
    int g = lane >> 3;
    int r = (lane & 7) + (g & 1) * 8;
    int c = (g >> 1) * 8;

    for (int jt = 0; jt < NJT; jt++) {
        __syncthreads();   // pT[jt&1] built; gT[(jt+1)&1] free (mma jt-1 done)

        if (jt < NJT - 1) {
            pv_load_gt(sm, (jt + 1) & 1, jbase + ((jt + 1) << 7), tid);
            asm volatile("cp.async.wait_group 1;" ::: "memory");
        } else {
            asm volatile("cp.async.wait_group 0;" ::: "memory");
        }

        const char* pb = smem + OFF_PT + (jt & 1) * PT_STRIDE;
        const char* hb = smem + OFF_GT + (jt & 1) * GT_STRIDE;
#pragma unroll
        for (int ks = 0; ks < 8; ks++) {
            uint32_t a0, a1, a2, a3;
            ldsm4(a0, a1, a2, a3, pb + (mi + r) * 272 + (ks * 16 + c) * 2);
            if ((wid & 3) == 0) mma16816(accz, a0, a1, a2, a3, ONES, ONES);
            uint32_t b0, b1r, b2, b3;
            ldsm4t(b0, b1r, b2, b3, hb + (ks * 16 + r) * 144 + (nb + c) * 2);
            mma16816(acc[0], a0, a1, a2, a3, b0, b1r);
            mma16816(acc[1], a0, a1, a2, a3, b2, b3);
        }

        if (jt < NJT - 1) {
            pv_build(smem, (jt + 1) & 1, jbase + ((jt + 1) << 7), Ac, UX, UX2, il, jc);
            if (jt < NJT - 2) {
#pragma unroll
                for (int q = 0; q < 4; q++) Ac[q] = __ldcs(arow + (long)(jt + 2) * 32 + q);
            }
        }
    }

    // write fp32 partials (no division here)
    int r0 = mi + (lane >> 2);
    float* P0 = g_Part + ((size_t)jhalf * NN + (i0 + r0)) * PROW;
    float* P1 = P0 + 8 * PROW;
#pragma unroll
    for (int h = 0; h < 2; h++) {
        int cb = nb + h * 8 + (lane & 3) * 2;
        P0[cb] = acc[h][0];
        P0[cb + 1] = acc[h][1];
        P1[cb] = acc[h][2];
        P1[cb + 1] = acc[h][3];
    }
    if (((wid & 3) == 0) && ((lane & 3) == 0)) {
        P0[64] = accz[0];
        P1[64] = accz[2];
    }
}

// ---------------- k_fin: combine split-j partials + sigmoid ----------------
__global__ void k_fin(const float* __restrict__ beta, float* __restrict__ out) {
    int idx = blockIdx.x * 256 + threadIdx.x;
    if (idx >= NN * OUTD) return;
    int rr = idx >> 6, cc = idx & 63;
    const float* p0 = g_Part + (size_t)rr * PROW;
    const float* p1 = g_Part + ((size_t)NN + rr) * PROW;
    float n = p0[cc] + p1[cc];
    float z = p0[64] + p1[64];
    out[idx] = 1.f / (1.f + expf(-(n / z + beta[cc])));
}

// ---------------- launch: k_pv at profiled index 3 ----------------
extern "C" void kernel_launch(void* const* d_in, const int* in_sizes, int n_in,
                              void* d_out, int out_size) {
    const float* X = (const float*)d_in[0];
    const int* A = (const int*)d_in[1];
    const float* W1 = (const float*)d_in[2];
    const float* b1 = (const float*)d_in[3];
    const float* a = (const float*)d_in[4];
    const float* Omega = (const float*)d_in[5];
    const float* beta = (const float*)d_in[6];
    float* out = (float*)d_out;

    cudaFuncSetAttribute(k_pv, cudaFuncAttributeMaxDynamicSharedMemorySize, SMEM_PV);

    k_prep<<<IND + 1, 128>>>(W1, b1, a, Omega);
    k_sg<<<NN / 64, 256>>>(X);
    k_maxuv<<<1, 1024>>>();
    k_pv<<<(NN / 32) * 2, 256, SMEM_PV>>>(A);
    k_fin<<<(NN * OUTD + 255) / 256, 256>>>(beta, out);
}